// round 1
// baseline (speedup 1.0000x reference)
#include <cuda_runtime.h>
#include <math.h>

#define BN 128
#define LN 105
#define MN 55
#define DN 256
#define ELN 3
static constexpr int BM = BN * MN;     // 7040
static constexpr int LL = LN * LN;     // 11025
static constexpr float SCALE = 0.0625f; // 1/sqrt(256)

// ---------------- scratch (device globals; no allocation allowed) ----------------
__device__ float g_xt[BM * LN];              // normalized, transposed x  [bm][L]
__device__ float g_z[(size_t)BM * 35 * DN];  // embeddings, max T=35
__device__ float g_wT[3 * 35 * DN];          // transposed conv weights, max C=35
__device__ float g_meff[ELN * DN * DN];      // Wq @ Wk^T per layer
__device__ float g_u[ELN * DN];              // Wq @ bk
__device__ float g_v[ELN * DN];              // Wk @ bq
__device__ float g_cc[ELN];                  // bq . bk
__device__ float g_S[(size_t)BM * 35 * 35];  // per-(b,m) softmax rows

// ---------------- RevIN + transpose ----------------
__global__ void revin_kernel(const float* __restrict__ x) {
    __shared__ float sx[LN * MN];
    __shared__ float smean[MN], sinv[MN];
    int b = blockIdx.x;
    const float* xb = x + (size_t)b * LN * MN;
    for (int i = threadIdx.x; i < LN * MN; i += blockDim.x) sx[i] = xb[i];
    __syncthreads();
    for (int m = threadIdx.x; m < MN; m += blockDim.x) {
        float s = 0.f, s2 = 0.f;
        for (int l = 0; l < LN; l++) { float v = sx[l * MN + m]; s += v; s2 += v * v; }
        float mean = s * (1.0f / LN);
        float var = s2 * (1.0f / LN) - mean * mean;
        smean[m] = mean;
        sinv[m] = rsqrtf(var + 1e-5f);
    }
    __syncthreads();
    float* ob = g_xt + (size_t)b * MN * LN;
    for (int i = threadIdx.x; i < MN * LN; i += blockDim.x) {
        int m = i / LN, l = i - m * LN;
        ob[i] = (sx[l * MN + m] - smean[m]) * sinv[m];
    }
}

// ---------------- Meff = Wq @ Wk^T per layer ----------------
__global__ void meff_kernel(const float* __restrict__ Wq, const float* __restrict__ Wk) {
    int l = blockIdx.z;
    int i0 = blockIdx.y * 16, j0 = blockIdx.x * 16;
    __shared__ float sq[16][17], sk[16][17];
    int ty = threadIdx.y, tx = threadIdx.x;
    float acc = 0.f;
    const float* wq = Wq + (size_t)l * DN * DN;
    const float* wk = Wk + (size_t)l * DN * DN;
    for (int k0 = 0; k0 < DN; k0 += 16) {
        sq[ty][tx] = wq[(i0 + ty) * DN + k0 + tx];
        sk[ty][tx] = wk[(j0 + ty) * DN + k0 + tx];
        __syncthreads();
#pragma unroll
        for (int kk = 0; kk < 16; kk++) acc += sq[ty][kk] * sk[tx][kk];
        __syncthreads();
    }
    g_meff[(size_t)l * DN * DN + (i0 + ty) * DN + j0 + tx] = acc;
}

__global__ void uvc_kernel(const float* __restrict__ Wq, const float* __restrict__ Wk,
                           const float* __restrict__ bq, const float* __restrict__ bk) {
    int l = blockIdx.x;
    int k = threadIdx.x;
    float su = 0.f, sv = 0.f;
    for (int d = 0; d < DN; d++) {
        su += Wq[(size_t)l * DN * DN + k * DN + d] * bk[l * DN + d];
        sv += Wk[(size_t)l * DN * DN + k * DN + d] * bq[l * DN + d];
    }
    g_u[l * DN + k] = su;
    g_v[l * DN + k] = sv;
    if (k == 0) {
        float c = 0.f;
        for (int d = 0; d < DN; d++) c += bq[l * DN + d] * bk[l * DN + d];
        g_cc[l] = c;
    }
}

// ---------------- conv weight transpose: w[d][c][t] -> wT[(c*3+t)][d] ----------------
__global__ void wtrans_kernel(const float* __restrict__ w, int C) {
    int i = blockIdx.x * blockDim.x + threadIdx.x;
    int tot = DN * C * 3;
    if (i < tot) {
        int d = i / (C * 3);
        int r = i - d * (C * 3);
        g_wT[r * DN + d] = w[i];
    }
}

// ---------------- circular conv1d (kernel 3, wrap) + positional embedding ----------------
// input: xt row reshaped [T][C] (T*C = L), weights wT[(c*3+t)*DN+d]
// z[bm][t][d] = pe(T)[t][d] + sum_{c,k} wT[c*3+k][d] * x[(t-1+k) mod T][c]
template <int T, int C>
__global__ __launch_bounds__(256) void conv_embed_kernel() {
    constexpr int CHUNK = 8;
    __shared__ float sx[LN];
    __shared__ float sw[3 * CHUNK * DN];
    int bm = blockIdx.x;
    int d = threadIdx.x;
    for (int i = threadIdx.x; i < LN; i += blockDim.x) sx[i] = g_xt[(size_t)bm * LN + i];
    float acc[T];
#pragma unroll
    for (int t = 0; t < T; t++) acc[t] = 0.f;
    for (int c0 = 0; c0 < C; c0 += CHUNK) {
        int cw = (C - c0 < CHUNK) ? (C - c0) : CHUNK;
        __syncthreads();
        for (int i = threadIdx.x; i < cw * 3 * DN; i += blockDim.x)
            sw[i] = g_wT[c0 * 3 * DN + i];
        __syncthreads();
        for (int ci = 0; ci < cw; ci++) {
            int c = c0 + ci;
            float w0 = sw[(ci * 3 + 0) * DN + d];
            float w1 = sw[(ci * 3 + 1) * DN + d];
            float w2 = sw[(ci * 3 + 2) * DN + d];
#pragma unroll
            for (int t = 0; t < T; t++) {
                int tm = (t == 0) ? (T - 1) : (t - 1);
                int tp = (t == T - 1) ? 0 : (t + 1);
                acc[t] += w0 * sx[tm * C + c] + w1 * sx[t * C + c] + w2 * sx[tp * C + c];
            }
        }
    }
    float freq = expf(-(float)(2 * (d >> 1)) * (9.210340371976184f / 256.f));
    bool isodd = (d & 1);
#pragma unroll
    for (int t = 0; t < T; t++) {
        float arg = (float)t * freq;
        float pe = isodd ? cosf(arg) : sinf(arg);
        g_z[((size_t)bm * T + t) * DN + d] = acc[t] + pe;
    }
}

// ---------------- fused attention: S = softmax(scale*(Z Meff Z^T + Zu + (Zv)^T + c)) ----------------
template <int T>
__global__ __launch_bounds__(256) void attn_kernel(int layer) {
    constexpr int TP = (T + 3) & ~3;
    constexpr int TT = T * T;
    extern __shared__ float sm[];
    float* sZt = sm;            // [DN][TP]  transposed Z
    float* sG = sm + DN * TP;   // [T][DN]
    __shared__ float szu[64], szv[64];

    int bm = blockIdx.x;
    int d = threadIdx.x;
    const float* zb = g_z + (size_t)bm * T * DN;
#pragma unroll
    for (int t = 0; t < T; t++) sZt[d * TP + t] = zb[t * DN + d];
#pragma unroll
    for (int t = T; t < TP; t++) sZt[d * TP + t] = 0.f;
    __syncthreads();

    // zu/zv (bias cross terms)
    const float* uu = g_u + layer * DN;
    const float* vv = g_v + layer * DN;
    if (d < T) {
        float su = 0.f, sv = 0.f;
        for (int k = 0; k < DN; k++) {
            float z = sZt[k * TP + d];
            su += z * uu[k];
            sv += z * vv[k];
        }
        szu[d] = su;
        szv[d] = sv;
    }

    // phase G: G = Z @ Meff   (thread d owns column d; acc[t] in registers)
    const float* Mf = g_meff + (size_t)layer * DN * DN;
    float acc[TP];
#pragma unroll
    for (int t = 0; t < TP; t++) acc[t] = 0.f;
#pragma unroll 2
    for (int k = 0; k < DN; k++) {
        float m = __ldg(&Mf[k * DN + d]);
        const float4* zc = (const float4*)(sZt + k * TP);
#pragma unroll
        for (int t4 = 0; t4 < TP / 4; t4++) {
            float4 z4 = zc[t4];
            acc[t4 * 4 + 0] += z4.x * m;
            acc[t4 * 4 + 1] += z4.y * m;
            acc[t4 * 4 + 2] += z4.z * m;
            acc[t4 * 4 + 3] += z4.w * m;
        }
    }
#pragma unroll
    for (int t = 0; t < T; t++) sG[t * DN + d] = acc[t];
    __syncthreads();

    // phase S: per-row dot + softmax, write probabilities
    int w = d >> 5, e = d & 31;
    float cterm = g_cc[layer];
    float* Sout = g_S + (size_t)bm * TT;
    for (int l = w; l < T; l += 8) {
        const float4* gl = (const float4*)(sG + l * DN);
        float d0 = 0.f, d1 = 0.f;
#pragma unroll 16
        for (int q = 0; q < DN / 4; q++) {
            float4 g4 = gl[q];
            int dd = q * 4;
            d0 += g4.x * sZt[(dd + 0) * TP + e] + g4.y * sZt[(dd + 1) * TP + e] +
                  g4.z * sZt[(dd + 2) * TP + e] + g4.w * sZt[(dd + 3) * TP + e];
            if (T > 32) {
                d1 += g4.x * sZt[(dd + 0) * TP + e + 32] + g4.y * sZt[(dd + 1) * TP + e + 32] +
                      g4.z * sZt[(dd + 2) * TP + e + 32] + g4.w * sZt[(dd + 3) * TP + e + 32];
            }
        }
        bool v0 = (e < T);
        bool v1 = (T > 32) && (e + 32 < T);
        float zul = szu[l];
        float x0 = v0 ? SCALE * (d0 + zul + szv[e] + cterm) : -1e30f;
        float x1 = v1 ? SCALE * (d1 + zul + szv[e + 32] + cterm) : -1e30f;
        float mx = fmaxf(x0, x1);
#pragma unroll
        for (int o = 16; o; o >>= 1) mx = fmaxf(mx, __shfl_xor_sync(0xffffffffu, mx, o));
        float e0 = v0 ? __expf(x0 - mx) : 0.f;
        float e1 = v1 ? __expf(x1 - mx) : 0.f;
        float ssum = e0 + e1;
#pragma unroll
        for (int o = 16; o; o >>= 1) ssum += __shfl_xor_sync(0xffffffffu, ssum, o);
        float inv = 1.0f / ssum;
        if (v0) Sout[l * T + e] = e0 * inv;
        if (v1) Sout[l * T + e + 32] = e1 * inv;
    }
}

// ---------------- channel mean + repeat/tile expansion ----------------
// series (TILE=false): out[l][s] = A[l/P][s/P] ; prior (TILE=true, T==P): out[l][s] = A[l%P][s%P]
template <int T, int P, bool TILE>
__global__ __launch_bounds__(256) void reduce_expand_kernel(float* __restrict__ out) {
    __shared__ float sA[T * T];
    int b = blockIdx.x;
    const float* Sb = g_S + (size_t)b * MN * T * T;
    for (int r = threadIdx.x; r < T * T; r += blockDim.x) {
        float s = 0.f;
#pragma unroll 5
        for (int m = 0; m < MN; m++) s += Sb[(size_t)m * T * T + r];
        sA[r] = s * (1.0f / MN);
    }
    __syncthreads();
    float* ob = out + (size_t)b * LL;
    for (int i = threadIdx.x; i < LL; i += blockDim.x) {
        int l = i / LN, s = i - l * LN;
        int al, as;
        if (TILE) { al = l % P; as = s % P; }
        else      { al = l / P; as = s / P; }
        ob[i] = sA[al * T + as];
    }
}

// ---------------- host orchestration ----------------
static inline int attn_smem_bytes(int T) {
    int TP = (T + 3) & ~3;
    return (DN * TP + T * DN) * 4;
}

template <int T, int C>
static void run_conv(const float* w) {
    wtrans_kernel<<<(DN * C * 3 + 255) / 256, 256>>>(w, C);
    conv_embed_kernel<T, C><<<BM, 256>>>();
}

template <int T, int P, bool TILE>
static void run_attn_layers(float* outbase) {
    int smem = attn_smem_bytes(T);
    cudaFuncSetAttribute(attn_kernel<T>, cudaFuncAttributeMaxDynamicSharedMemorySize, smem);
    for (int l = 0; l < ELN; l++) {
        attn_kernel<T><<<BM, 256, smem>>>(l);
        reduce_expand_kernel<T, P, TILE><<<BN, 256>>>(outbase + (size_t)l * BN * LL);
    }
}

extern "C" void kernel_launch(void* const* d_in, const int* in_sizes, int n_in,
                              void* d_out, int out_size) {
    const float* x = (const float*)d_in[0];
    const float* Wq = (const float*)d_in[7];
    const float* bq = (const float*)d_in[8];
    const float* Wk = (const float*)d_in[9];
    const float* bk = (const float*)d_in[10];
    float* out = (float*)d_out;

    revin_kernel<<<BN, 256>>>(x);
    meff_kernel<<<dim3(16, 16, ELN), dim3(16, 16)>>>(Wq, Wk);
    uvc_kernel<<<ELN, 256>>>(Wq, Wk, bq, bk);

    // patch 0: p=3, n=35
    run_conv<35, 3>((const float*)d_in[1]);
    run_attn_layers<35, 3, false>(out + (size_t)0 * BN * LL);
    run_conv<3, 35>((const float*)d_in[2]);
    run_attn_layers<3, 3, true>(out + (size_t)9 * BN * LL);

    // patch 1: p=5, n=21
    run_conv<21, 5>((const float*)d_in[3]);
    run_attn_layers<21, 5, false>(out + (size_t)3 * BN * LL);
    run_conv<5, 21>((const float*)d_in[4]);
    run_attn_layers<5, 5, true>(out + (size_t)12 * BN * LL);

    // patch 2: p=7, n=15
    run_conv<15, 7>((const float*)d_in[5]);
    run_attn_layers<15, 7, false>(out + (size_t)6 * BN * LL);
    run_conv<7, 15>((const float*)d_in[6]);
    run_attn_layers<7, 7, true>(out + (size_t)15 * BN * LL);
}

// round 3
// speedup vs baseline: 1.8684x; 1.8684x over previous
#include <cuda_runtime.h>
#include <cuda_bf16.h>
#include <math.h>
#include <cstdint>

#define BN 128
#define LN 105
#define MN 55
#define DN 256
#define ELN 3
static constexpr int BM = BN * MN;      // 7040
static constexpr int LL = LN * LN;      // 11025
static constexpr float SCALE = 0.0625f; // 1/sqrt(256)

// ---------------- scratch (device globals) ----------------
__device__ float g_xt[BM * LN];
__device__ float g_z[(size_t)BM * 35 * DN];                // fp32 embeddings (max T=35)
__device__ __nv_bfloat16 g_zh[(size_t)BM * 35 * DN];       // bf16 hi
__device__ __nv_bfloat16 g_zl[(size_t)BM * 35 * DN];       // bf16 lo
__device__ float g_wT[3 * 35 * DN];
__device__ float g_meff[ELN * DN * DN];                    // Wq @ Wk^T
__device__ __nv_bfloat16 g_mth[ELN * DN * DN];             // MeffT hi  [n][k]
__device__ __nv_bfloat16 g_mtl[ELN * DN * DN];             // MeffT lo
__device__ float g_u[ELN * DN];
__device__ float g_v[ELN * DN];
__device__ float g_cc[ELN];
__device__ float g_G[(size_t)ELN * BM * 35 * DN];          // G = Z @ Meff (per layer)
__device__ float g_S[(size_t)ELN * BM * 35 * 35];          // softmax rows
__device__ float g_A[(size_t)ELN * BN * 35 * 35];          // channel means

// ---------------- small helpers ----------------
__device__ __forceinline__ uint32_t smem_u32(const void* p) {
    uint32_t a;
    asm("{ .reg .u64 t; cvta.to.shared.u64 t, %1; cvt.u32.u64 %0, t; }" : "=r"(a) : "l"(p));
    return a;
}
__device__ __forceinline__ void cp_async16(uint32_t saddr, const void* gptr) {
    asm volatile("cp.async.ca.shared.global [%0], [%1], 16;" :: "r"(saddr), "l"(gptr) : "memory");
}
__device__ __forceinline__ void mma16816(float* d, const uint32_t* a, uint32_t b0, uint32_t b1) {
    asm volatile(
        "mma.sync.aligned.m16n8k16.row.col.f32.bf16.bf16.f32 "
        "{%0,%1,%2,%3}, {%4,%5,%6,%7}, {%8,%9}, {%0,%1,%2,%3};"
        : "+f"(d[0]), "+f"(d[1]), "+f"(d[2]), "+f"(d[3])
        : "r"(a[0]), "r"(a[1]), "r"(a[2]), "r"(a[3]), "r"(b0), "r"(b1));
}
#define LDMX4(r0, r1, r2, r3, addr) \
    asm volatile("ldmatrix.sync.aligned.m8n8.x4.shared.b16 {%0,%1,%2,%3}, [%4];" \
        : "=r"(r0), "=r"(r1), "=r"(r2), "=r"(r3) : "r"(addr))

// ---------------- RevIN + transpose ----------------
__global__ void revin_kernel(const float* __restrict__ x) {
    __shared__ float sx[LN * MN];
    __shared__ float smean[MN], sinv[MN];
    int b = blockIdx.x;
    const float* xb = x + (size_t)b * LN * MN;
    for (int i = threadIdx.x; i < LN * MN; i += blockDim.x) sx[i] = xb[i];
    __syncthreads();
    for (int m = threadIdx.x; m < MN; m += blockDim.x) {
        float s = 0.f, s2 = 0.f;
        for (int l = 0; l < LN; l++) { float v = sx[l * MN + m]; s += v; s2 += v * v; }
        float mean = s * (1.0f / LN);
        float var = s2 * (1.0f / LN) - mean * mean;
        smean[m] = mean;
        sinv[m] = rsqrtf(var + 1e-5f);
    }
    __syncthreads();
    float* ob = g_xt + (size_t)b * MN * LN;
    for (int i = threadIdx.x; i < MN * LN; i += blockDim.x) {
        int m = i / LN, l = i - m * LN;
        ob[i] = (sx[l * MN + m] - smean[m]) * sinv[m];
    }
}

// ---------------- Meff = Wq @ Wk^T ----------------
__global__ void meff_kernel(const float* __restrict__ Wq, const float* __restrict__ Wk) {
    int l = blockIdx.z;
    int i0 = blockIdx.y * 16, j0 = blockIdx.x * 16;
    __shared__ float sq[16][17], sk[16][17];
    int ty = threadIdx.y, tx = threadIdx.x;
    float acc = 0.f;
    const float* wq = Wq + (size_t)l * DN * DN;
    const float* wk = Wk + (size_t)l * DN * DN;
    for (int k0 = 0; k0 < DN; k0 += 16) {
        sq[ty][tx] = wq[(i0 + ty) * DN + k0 + tx];
        sk[ty][tx] = wk[(j0 + ty) * DN + k0 + tx];
        __syncthreads();
#pragma unroll
        for (int kk = 0; kk < 16; kk++) acc += sq[ty][kk] * sk[tx][kk];
        __syncthreads();
    }
    g_meff[(size_t)l * DN * DN + (i0 + ty) * DN + j0 + tx] = acc;
}

// MeffT split to bf16 hi/lo: mth[l][n][k] = bf16(meff[l][k][n])
__global__ void meffT_kernel() {
    int l = blockIdx.y;
    int i = blockIdx.x * 256 + threadIdx.x;   // n*256+k
    int n = i >> 8, k = i & 255;
    float v = g_meff[(size_t)l * DN * DN + k * DN + n];
    __nv_bfloat16 h = __float2bfloat16(v);
    g_mth[(size_t)l * DN * DN + i] = h;
    g_mtl[(size_t)l * DN * DN + i] = __float2bfloat16(v - __bfloat162float(h));
}

__global__ void uvc_kernel(const float* __restrict__ Wq, const float* __restrict__ Wk,
                           const float* __restrict__ bq, const float* __restrict__ bk) {
    int l = blockIdx.x;
    int k = threadIdx.x;
    float su = 0.f, sv = 0.f;
    for (int d = 0; d < DN; d++) {
        su += Wq[(size_t)l * DN * DN + k * DN + d] * bk[l * DN + d];
        sv += Wk[(size_t)l * DN * DN + k * DN + d] * bq[l * DN + d];
    }
    g_u[l * DN + k] = su;
    g_v[l * DN + k] = sv;
    if (k == 0) {
        float c = 0.f;
        for (int d = 0; d < DN; d++) c += bq[l * DN + d] * bk[l * DN + d];
        g_cc[l] = c;
    }
}

// ---------------- conv weight transpose ----------------
__global__ void wtrans_kernel(const float* __restrict__ w, int C) {
    int i = blockIdx.x * blockDim.x + threadIdx.x;
    int tot = DN * C * 3;
    if (i < tot) {
        int d = i / (C * 3);
        int r = i - d * (C * 3);
        g_wT[r * DN + d] = w[i];
    }
}

// ---------------- circular conv + PE -> Z (fp32 + bf16 split) ----------------
template <int T, int C>
__global__ __launch_bounds__(256) void conv_embed_kernel() {
    constexpr int CHUNK = 8;
    __shared__ float sx[LN];
    __shared__ float sw[3 * CHUNK * DN];
    int bm = blockIdx.x;
    int d = threadIdx.x;
    for (int i = threadIdx.x; i < LN; i += blockDim.x) sx[i] = g_xt[(size_t)bm * LN + i];
    float acc[T];
#pragma unroll
    for (int t = 0; t < T; t++) acc[t] = 0.f;
    for (int c0 = 0; c0 < C; c0 += CHUNK) {
        int cw = (C - c0 < CHUNK) ? (C - c0) : CHUNK;
        __syncthreads();
        for (int i = threadIdx.x; i < cw * 3 * DN; i += blockDim.x)
            sw[i] = g_wT[c0 * 3 * DN + i];
        __syncthreads();
        for (int ci = 0; ci < cw; ci++) {
            int c = c0 + ci;
            float w0 = sw[(ci * 3 + 0) * DN + d];
            float w1 = sw[(ci * 3 + 1) * DN + d];
            float w2 = sw[(ci * 3 + 2) * DN + d];
#pragma unroll
            for (int t = 0; t < T; t++) {
                int tm = (t == 0) ? (T - 1) : (t - 1);
                int tp = (t == T - 1) ? 0 : (t + 1);
                acc[t] += w0 * sx[tm * C + c] + w1 * sx[t * C + c] + w2 * sx[tp * C + c];
            }
        }
    }
    float freq = expf(-(float)(2 * (d >> 1)) * (9.210340371976184f / 256.f));
    bool isodd = (d & 1);
#pragma unroll
    for (int t = 0; t < T; t++) {
        float arg = (float)t * freq;
        float pe = isodd ? cosf(arg) : sinf(arg);
        float zv = acc[t] + pe;
        size_t ridx = ((size_t)bm * T + t) * DN + d;
        g_z[ridx] = zv;
        __nv_bfloat16 h = __float2bfloat16(zv);
        g_zh[ridx] = h;
        g_zl[ridx] = __float2bfloat16(zv - __bfloat162float(h));
    }
}

// ---------------- HMMA GEMM: G = Z @ Meff (bf16 3-split, mma.sync) ----------------
// grid: x = ntile*3+layer (6, fastest -> A-tile L2 reuse), y = rowtile (128 rows)
// block 256 thr (8 warps, 4m x 2n), warp tile 32x64, K = 12 chunks of 64
// smem: A[2][128][64]bf16 @ 0/16384, B[2][128][64]bf16 @ 32768/49152  (xor-swizzled)
static constexpr int GEMM_SMEM = 65536;

__global__ __launch_bounds__(256, 2) void gemm_kernel(int totrows) {
    extern __shared__ __align__(128) char smem[];
    const int tid = threadIdx.x;
    const int lane = tid & 31;
    const int wid = tid >> 5;
    const int wm = wid >> 1, wn = wid & 1;
    const int layer = blockIdx.x % 3;
    const int ntile = blockIdx.x / 3;
    const size_t m0 = (size_t)blockIdx.y * 128;
    const int n0 = ntile * 128;

    const uint32_t sb = smem_u32(smem);

    const __nv_bfloat16* Azh = g_zh + m0 * DN;
    const __nv_bfloat16* Azl = g_zl + m0 * DN;
    const __nv_bfloat16* Bh = g_mth + (size_t)layer * DN * DN + (size_t)n0 * DN;
    const __nv_bfloat16* Bl = g_mtl + (size_t)layer * DN * DN + (size_t)n0 * DN;

    float d[2][8][4];
#pragma unroll
    for (int i = 0; i < 2; i++)
#pragma unroll
        for (int j = 0; j < 8; j++)
#pragma unroll
            for (int q = 0; q < 4; q++) d[i][j][q] = 0.f;

    // chunk it: kc = it/3, split s = it%3 (zh,zh,zl adjacent for L2 reuse)
#define ISSUE_CHUNK(it, buf)                                                      \
    do {                                                                          \
        int kc_ = (it) / 3, s_ = (it) % 3;                                        \
        const __nv_bfloat16* As_ = ((s_ < 2) ? Azh : Azl) + kc_ * 64;             \
        const __nv_bfloat16* Bs_ = ((s_ == 1) ? Bl : Bh) + kc_ * 64;              \
        uint32_t sa_ = sb + (buf) * 16384;                                        \
        uint32_t sB_ = sb + 32768 + (buf) * 16384;                                \
        _Pragma("unroll")                                                         \
        for (int i_ = 0; i_ < 4; i_++) {                                          \
            int lin_ = i_ * 256 + tid;                                            \
            int row_ = lin_ >> 3, ch_ = lin_ & 7;                                 \
            uint32_t off_ = row_ * 128 + ((ch_ ^ (row_ & 7)) << 4);               \
            cp_async16(sa_ + off_, As_ + (size_t)row_ * DN + ch_ * 8);            \
            cp_async16(sB_ + off_, Bs_ + (size_t)row_ * DN + ch_ * 8);            \
        }                                                                         \
        asm volatile("cp.async.commit_group;" ::: "memory");                      \
    } while (0)

    ISSUE_CHUNK(0, 0);
    const int rA = lane & 15;
    const int chsel = lane >> 4;

    for (int it = 0; it < 12; it++) {
        if (it + 1 < 12) {
            ISSUE_CHUNK(it + 1, (it + 1) & 1);
            asm volatile("cp.async.wait_group 1;" ::: "memory");
        } else {
            asm volatile("cp.async.wait_group 0;" ::: "memory");
        }
        __syncthreads();
        {
            const int buf = it & 1;
            uint32_t sa = sb + buf * 16384;
            uint32_t sB = sb + 32768 + buf * 16384;
#pragma unroll
            for (int ks = 0; ks < 4; ks++) {
                uint32_t a[2][4];
#pragma unroll
                for (int mt = 0; mt < 2; mt++) {
                    int row = wm * 32 + mt * 16 + rA;
                    int ch = ks * 2 + chsel;
                    uint32_t addr = sa + row * 128 + ((ch ^ (row & 7)) << 4);
                    LDMX4(a[mt][0], a[mt][1], a[mt][2], a[mt][3], addr);
                }
#pragma unroll
                for (int ng = 0; ng < 4; ng++) {
                    uint32_t b0, b1, b2, b3;
                    int row = wn * 64 + ng * 16 + rA;
                    int ch = ks * 2 + chsel;
                    uint32_t addr = sB + row * 128 + ((ch ^ (row & 7)) << 4);
                    LDMX4(b0, b1, b2, b3, addr);
#pragma unroll
                    for (int mt = 0; mt < 2; mt++) {
                        mma16816(d[mt][ng * 2 + 0], a[mt], b0, b2);
                        mma16816(d[mt][ng * 2 + 1], a[mt], b1, b3);
                    }
                }
            }
        }
        __syncthreads();
    }
#undef ISSUE_CHUNK

    // epilogue
    float* Gbase = g_G + (size_t)layer * totrows * DN;
    int r0 = (int)m0 + wm * 32 + (lane >> 2);
    int c0 = n0 + wn * 64 + (lane & 3) * 2;
#pragma unroll
    for (int mt = 0; mt < 2; mt++) {
#pragma unroll
        for (int ng = 0; ng < 8; ng++) {
            int row = r0 + mt * 16;
            int col = c0 + ng * 8;
            *(float2*)(Gbase + (size_t)row * DN + col) = make_float2(d[mt][ng][0], d[mt][ng][1]);
            *(float2*)(Gbase + (size_t)(row + 8) * DN + col) = make_float2(d[mt][ng][2], d[mt][ng][3]);
        }
    }
}

// ---------------- S-phase: logits + softmax ----------------
template <int T>
__global__ __launch_bounds__(256) void sphase_kernel(int totrows) {
    constexpr int TP = (T + 3) & ~3;
    constexpr int TT = T * T;
    extern __shared__ float sm[];
    float* sZt = sm;            // [DN][TP]
    float* sG = sm + DN * TP;   // [T][DN]
    __shared__ float szu[64], szv[64];

    int bm = blockIdx.x;
    int layer = blockIdx.y;
    int d = threadIdx.x;
    const float* zb = g_z + (size_t)bm * T * DN;
#pragma unroll
    for (int t = 0; t < T; t++) sZt[d * TP + t] = zb[t * DN + d];
#pragma unroll
    for (int t = T; t < TP; t++) sZt[d * TP + t] = 0.f;
    const float* gb = g_G + ((size_t)layer * totrows + (size_t)bm * T) * DN;
    for (int i = d; i < T * DN / 4; i += 256) ((float4*)sG)[i] = ((const float4*)gb)[i];
    __syncthreads();

    const float* uu = g_u + layer * DN;
    const float* vv = g_v + layer * DN;
    if (d < T) {
        float su = 0.f, sv = 0.f;
        for (int k = 0; k < DN; k++) {
            float z = sZt[k * TP + d];
            su += z * uu[k];
            sv += z * vv[k];
        }
        szu[d] = su;
        szv[d] = sv;
    }
    __syncthreads();

    int w = d >> 5, e = d & 31;
    float cterm = g_cc[layer];
    float* Sout = g_S + ((size_t)layer * BM + bm) * TT;
    for (int l = w; l < T; l += 8) {
        const float4* gl = (const float4*)(sG + l * DN);
        float d0 = 0.f, d1 = 0.f;
#pragma unroll 16
        for (int q = 0; q < DN / 4; q++) {
            float4 g4 = gl[q];
            int dd = q * 4;
            d0 += g4.x * sZt[(dd + 0) * TP + e] + g4.y * sZt[(dd + 1) * TP + e] +
                  g4.z * sZt[(dd + 2) * TP + e] + g4.w * sZt[(dd + 3) * TP + e];
            if (T > 32) {
                d1 += g4.x * sZt[(dd + 0) * TP + e + 32] + g4.y * sZt[(dd + 1) * TP + e + 32] +
                      g4.z * sZt[(dd + 2) * TP + e + 32] + g4.w * sZt[(dd + 3) * TP + e + 32];
            }
        }
        bool v0 = (e < T);
        bool v1 = (T > 32) && (e + 32 < T);
        float zul = szu[l];
        float x0 = v0 ? SCALE * (d0 + zul + szv[e] + cterm) : -1e30f;
        float x1 = v1 ? SCALE * (d1 + zul + szv[e + 32] + cterm) : -1e30f;
        float mx = fmaxf(x0, x1);
#pragma unroll
        for (int o = 16; o; o >>= 1) mx = fmaxf(mx, __shfl_xor_sync(0xffffffffu, mx, o));
        float e0 = v0 ? __expf(x0 - mx) : 0.f;
        float e1 = v1 ? __expf(x1 - mx) : 0.f;
        float ssum = e0 + e1;
#pragma unroll
        for (int o = 16; o; o >>= 1) ssum += __shfl_xor_sync(0xffffffffu, ssum, o);
        float inv = 1.0f / ssum;
        if (v0) Sout[l * T + e] = e0 * inv;
        if (v1) Sout[l * T + e + 32] = e1 * inv;
    }
}

// ---------------- channel mean ----------------
template <int T>
__global__ __launch_bounds__(256) void mean_kernel() {
    constexpr int TT = T * T;
    int b = blockIdx.x, layer = blockIdx.y;
    const float* Sb = g_S + ((size_t)layer * BM + (size_t)b * MN) * TT;
    float* Ab = g_A + ((size_t)layer * BN + b) * TT;
    for (int r = threadIdx.x; r < TT; r += blockDim.x) {
        float s = 0.f;
#pragma unroll 5
        for (int m = 0; m < MN; m++) s += Sb[(size_t)m * TT + r];
        Ab[r] = s * (1.0f / MN);
    }
}

// ---------------- expand (repeat / tile) ----------------
template <int T, int P, bool TILE>
__global__ __launch_bounds__(256) void expand_kernel(float* __restrict__ out) {
    __shared__ float sA[T * T];
    int b = blockIdx.x, layer = blockIdx.y;
    const float* Ab = g_A + ((size_t)layer * BN + b) * T * T;
    for (int i = threadIdx.x; i < T * T; i += 256) sA[i] = Ab[i];
    __syncthreads();
    float* ob = out + ((size_t)layer * BN + b) * LL;
    for (int i = threadIdx.x; i < LL; i += 256) {
        int l = i / LN, s = i - l * LN;
        int al = TILE ? (l % P) : (l / P);
        int as = TILE ? (s % P) : (s / P);
        ob[i] = sA[al * T + as];
    }
}

// ---------------- host orchestration ----------------
static inline int sphase_smem_bytes(int T) {
    int TP = (T + 3) & ~3;
    return (DN * TP + T * DN) * 4;
}

template <int T, int C, int P, bool TILE>
static void run_branch(const float* w, float* outbase) {
    wtrans_kernel<<<(DN * C * 3 + 255) / 256, 256>>>(w, C);
    conv_embed_kernel<T, C><<<BM, 256>>>();
    int totrows = BM * T;
    gemm_kernel<<<dim3(6, totrows / 128), 256, GEMM_SMEM>>>(totrows);
    int smem = sphase_smem_bytes(T);
    cudaFuncSetAttribute(sphase_kernel<T>, cudaFuncAttributeMaxDynamicSharedMemorySize, smem);
    sphase_kernel<T><<<dim3(BM, ELN), 256, smem>>>(totrows);
    mean_kernel<T><<<dim3(BN, ELN), 256>>>();
    expand_kernel<T, P, TILE><<<dim3(BN, ELN), 256>>>(outbase);
}

extern "C" void kernel_launch(void* const* d_in, const int* in_sizes, int n_in,
                              void* d_out, int out_size) {
    const float* x = (const float*)d_in[0];
    const float* Wq = (const float*)d_in[7];
    const float* bq = (const float*)d_in[8];
    const float* Wk = (const float*)d_in[9];
    const float* bk = (const float*)d_in[10];
    float* out = (float*)d_out;

    cudaFuncSetAttribute(gemm_kernel, cudaFuncAttributeMaxDynamicSharedMemorySize, GEMM_SMEM);

    revin_kernel<<<BN, 256>>>(x);
    meff_kernel<<<dim3(16, 16, ELN), dim3(16, 16)>>>(Wq, Wk);
    meffT_kernel<<<dim3(256, ELN), 256>>>();
    uvc_kernel<<<ELN, 256>>>(Wq, Wk, bq, bk);

    run_branch<35, 3, 3, false>((const float*)d_in[1], out + (size_t)0 * BN * LL);
    run_branch<3, 35, 3, true>((const float*)d_in[2], out + (size_t)9 * BN * LL);

    run_branch<21, 5, 5, false>((const float*)d_in[3], out + (size_t)3 * BN * LL);
    run_branch<5, 21, 5, true>((const float*)d_in[4], out + (size_t)12 * BN * LL);

    run_branch<15, 7, 7, false>((const float*)d_in[5], out + (size_t)6 * BN * LL);
    run_branch<7, 15, 7, true>((const float*)d_in[6], out + (size_t)15 * BN * LL);
}

// round 4
// speedup vs baseline: 2.6655x; 1.4266x over previous
#include <cuda_runtime.h>
#include <cuda_bf16.h>
#include <math.h>
#include <cstdint>

#define BN 128
#define LN 105
#define MN 55
#define DN 256
#define ELN 3
static constexpr int BM = BN * MN;      // 7040
static constexpr int LL = LN * LN;      // 11025
static constexpr float SCALE = 0.0625f; // 1/sqrt(256)

// ---------------- scratch (device globals) ----------------
__device__ float g_xt[BM * LN];
__device__ __nv_bfloat16 g_zh[(size_t)BM * 35 * DN];
__device__ __nv_bfloat16 g_zl[(size_t)BM * 35 * DN];
__device__ float g_wT[3 * 35 * DN];
__device__ float g_meff[ELN * DN * DN];
__device__ __nv_bfloat16 g_mth[ELN * DN * DN];             // MeffT hi [n][k]
__device__ __nv_bfloat16 g_mtl[ELN * DN * DN];             // MeffT lo
__device__ float g_u[ELN * DN];
__device__ float g_v[ELN * DN];
__device__ float g_cc[ELN];
__device__ __nv_bfloat16 g_Gh[(size_t)ELN * BM * 35 * DN]; // G hi
__device__ __nv_bfloat16 g_Gl[(size_t)ELN * BM * 35 * DN]; // G lo
__device__ float g_S[(size_t)ELN * BM * 35 * 35];
__device__ float g_A[(size_t)ELN * BN * 35 * 35];

// ---------------- helpers ----------------
__device__ __forceinline__ uint32_t smem_u32(const void* p) {
    uint32_t a;
    asm("{ .reg .u64 t; cvta.to.shared.u64 t, %1; cvt.u32.u64 %0, t; }" : "=r"(a) : "l"(p));
    return a;
}
__device__ __forceinline__ void cp_async16(uint32_t saddr, const void* gptr) {
    asm volatile("cp.async.ca.shared.global [%0], [%1], 16;" :: "r"(saddr), "l"(gptr) : "memory");
}
__device__ __forceinline__ void mma16816(float* d, const uint32_t* a, uint32_t b0, uint32_t b1) {
    asm volatile(
        "mma.sync.aligned.m16n8k16.row.col.f32.bf16.bf16.f32 "
        "{%0,%1,%2,%3}, {%4,%5,%6,%7}, {%8,%9}, {%0,%1,%2,%3};"
        : "+f"(d[0]), "+f"(d[1]), "+f"(d[2]), "+f"(d[3])
        : "r"(a[0]), "r"(a[1]), "r"(a[2]), "r"(a[3]), "r"(b0), "r"(b1));
}
#define LDMX4(r0, r1, r2, r3, addr) \
    asm volatile("ldmatrix.sync.aligned.m8n8.x4.shared.b16 {%0,%1,%2,%3}, [%4];" \
        : "=r"(r0), "=r"(r1), "=r"(r2), "=r"(r3) : "r"(addr))

// ---------------- RevIN + transpose ----------------
__global__ void revin_kernel(const float* __restrict__ x) {
    __shared__ float sx[LN * MN];
    __shared__ float smean[MN], sinv[MN];
    int b = blockIdx.x;
    const float* xb = x + (size_t)b * LN * MN;
    for (int i = threadIdx.x; i < LN * MN; i += blockDim.x) sx[i] = xb[i];
    __syncthreads();
    for (int m = threadIdx.x; m < MN; m += blockDim.x) {
        float s = 0.f, s2 = 0.f;
        for (int l = 0; l < LN; l++) { float v = sx[l * MN + m]; s += v; s2 += v * v; }
        float mean = s * (1.0f / LN);
        float var = s2 * (1.0f / LN) - mean * mean;
        smean[m] = mean;
        sinv[m] = rsqrtf(var + 1e-5f);
    }
    __syncthreads();
    float* ob = g_xt + (size_t)b * MN * LN;
    for (int i = threadIdx.x; i < MN * LN; i += blockDim.x) {
        int m = i / LN, l = i - m * LN;
        ob[i] = (sx[l * MN + m] - smean[m]) * sinv[m];
    }
}

// ---------------- Meff = Wq @ Wk^T ----------------
__global__ void meff_kernel(const float* __restrict__ Wq, const float* __restrict__ Wk) {
    int l = blockIdx.z;
    int i0 = blockIdx.y * 16, j0 = blockIdx.x * 16;
    __shared__ float sq[16][17], sk[16][17];
    int ty = threadIdx.y, tx = threadIdx.x;
    float acc = 0.f;
    const float* wq = Wq + (size_t)l * DN * DN;
    const float* wk = Wk + (size_t)l * DN * DN;
    for (int k0 = 0; k0 < DN; k0 += 16) {
        sq[ty][tx] = wq[(i0 + ty) * DN + k0 + tx];
        sk[ty][tx] = wk[(j0 + ty) * DN + k0 + tx];
        __syncthreads();
#pragma unroll
        for (int kk = 0; kk < 16; kk++) acc += sq[ty][kk] * sk[tx][kk];
        __syncthreads();
    }
    g_meff[(size_t)l * DN * DN + (i0 + ty) * DN + j0 + tx] = acc;
}

__global__ void meffT_kernel() {
    int l = blockIdx.y;
    int i = blockIdx.x * 256 + threadIdx.x;   // n*256+k
    int n = i >> 8, k = i & 255;
    float v = g_meff[(size_t)l * DN * DN + k * DN + n];
    __nv_bfloat16 h = __float2bfloat16(v);
    g_mth[(size_t)l * DN * DN + i] = h;
    g_mtl[(size_t)l * DN * DN + i] = __float2bfloat16(v - __bfloat162float(h));
}

// u = Wq@bk, v = Wk@bq, cc = bq.bk   (warp per k, coalesced)
__global__ void uvc_kernel(const float* __restrict__ Wq, const float* __restrict__ Wk,
                           const float* __restrict__ bq, const float* __restrict__ bk) {
    int l = blockIdx.x;
    int wid = threadIdx.x >> 5, lane = threadIdx.x & 31;
    int k = blockIdx.y * 8 + wid;
    float su = 0.f, sv = 0.f;
    const float* wq = Wq + (size_t)l * DN * DN + (size_t)k * DN;
    const float* wk = Wk + (size_t)l * DN * DN + (size_t)k * DN;
    for (int d = lane; d < DN; d += 32) {
        su += wq[d] * bk[l * DN + d];
        sv += wk[d] * bq[l * DN + d];
    }
#pragma unroll
    for (int o = 16; o; o >>= 1) {
        su += __shfl_xor_sync(0xffffffffu, su, o);
        sv += __shfl_xor_sync(0xffffffffu, sv, o);
    }
    if (lane == 0) {
        g_u[l * DN + k] = su;
        g_v[l * DN + k] = sv;
    }
    if (blockIdx.y == 0 && wid == 0) {
        float c = 0.f;
        for (int d = lane; d < DN; d += 32) c += bq[l * DN + d] * bk[l * DN + d];
#pragma unroll
        for (int o = 16; o; o >>= 1) c += __shfl_xor_sync(0xffffffffu, c, o);
        if (lane == 0) g_cc[l] = c;
    }
}

// ---------------- conv weight transpose ----------------
__global__ void wtrans_kernel(const float* __restrict__ w, int C) {
    int i = blockIdx.x * blockDim.x + threadIdx.x;
    int tot = DN * C * 3;
    if (i < tot) {
        int d = i / (C * 3);
        int r = i - d * (C * 3);
        g_wT[r * DN + d] = w[i];
    }
}

// ---------------- circular conv + PE -> Z (bf16 hi/lo) ----------------
template <int T, int C>
__global__ __launch_bounds__(256) void conv_embed_kernel() {
    constexpr int CHUNK = 8;
    __shared__ float sx[LN];
    __shared__ float sw[3 * CHUNK * DN];
    int bm = blockIdx.x;
    int d = threadIdx.x;
    for (int i = threadIdx.x; i < LN; i += blockDim.x) sx[i] = g_xt[(size_t)bm * LN + i];
    float acc[T];
#pragma unroll
    for (int t = 0; t < T; t++) acc[t] = 0.f;
    for (int c0 = 0; c0 < C; c0 += CHUNK) {
        int cw = (C - c0 < CHUNK) ? (C - c0) : CHUNK;
        __syncthreads();
        for (int i = threadIdx.x; i < cw * 3 * DN; i += blockDim.x)
            sw[i] = g_wT[c0 * 3 * DN + i];
        __syncthreads();
        for (int ci = 0; ci < cw; ci++) {
            int c = c0 + ci;
            float w0 = sw[(ci * 3 + 0) * DN + d];
            float w1 = sw[(ci * 3 + 1) * DN + d];
            float w2 = sw[(ci * 3 + 2) * DN + d];
#pragma unroll
            for (int t = 0; t < T; t++) {
                int tm = (t == 0) ? (T - 1) : (t - 1);
                int tp = (t == T - 1) ? 0 : (t + 1);
                acc[t] += w0 * sx[tm * C + c] + w1 * sx[t * C + c] + w2 * sx[tp * C + c];
            }
        }
    }
    float freq = expf(-(float)(2 * (d >> 1)) * (9.210340371976184f / 256.f));
    bool isodd = (d & 1);
#pragma unroll
    for (int t = 0; t < T; t++) {
        float arg = (float)t * freq;
        float pe = isodd ? cosf(arg) : sinf(arg);
        float zv = acc[t] + pe;
        size_t ridx = ((size_t)bm * T + t) * DN + d;
        __nv_bfloat16 h = __float2bfloat16(zv);
        g_zh[ridx] = h;
        g_zl[ridx] = __float2bfloat16(zv - __bfloat162float(h));
    }
}

// ---------------- HMMA GEMM: G = Z @ Meff (bf16 3-split) ----------------
static constexpr int GEMM_SMEM = 65536;

__global__ __launch_bounds__(256, 2) void gemm_kernel(int totrows) {
    extern __shared__ __align__(128) char smem[];
    const int tid = threadIdx.x;
    const int lane = tid & 31;
    const int wid = tid >> 5;
    const int wm = wid >> 1, wn = wid & 1;
    const int layer = blockIdx.x % 3;
    const int ntile = blockIdx.x / 3;
    const size_t m0 = (size_t)blockIdx.y * 128;
    const int n0 = ntile * 128;

    const uint32_t sb = smem_u32(smem);

    const __nv_bfloat16* Azh = g_zh + m0 * DN;
    const __nv_bfloat16* Azl = g_zl + m0 * DN;
    const __nv_bfloat16* Bh = g_mth + (size_t)layer * DN * DN + (size_t)n0 * DN;
    const __nv_bfloat16* Bl = g_mtl + (size_t)layer * DN * DN + (size_t)n0 * DN;

    float d[2][8][4];
#pragma unroll
    for (int i = 0; i < 2; i++)
#pragma unroll
        for (int j = 0; j < 8; j++)
#pragma unroll
            for (int q = 0; q < 4; q++) d[i][j][q] = 0.f;

#define ISSUE_CHUNK(it, buf)                                                      \
    do {                                                                          \
        int kc_ = (it) / 3, s_ = (it) % 3;                                        \
        const __nv_bfloat16* As_ = ((s_ < 2) ? Azh : Azl) + kc_ * 64;             \
        const __nv_bfloat16* Bs_ = ((s_ == 1) ? Bl : Bh) + kc_ * 64;              \
        uint32_t sa_ = sb + (buf) * 16384;                                        \
        uint32_t sB_ = sb + 32768 + (buf) * 16384;                                \
        _Pragma("unroll")                                                         \
        for (int i_ = 0; i_ < 4; i_++) {                                          \
            int lin_ = i_ * 256 + tid;                                            \
            int row_ = lin_ >> 3, ch_ = lin_ & 7;                                 \
            uint32_t off_ = row_ * 128 + ((ch_ ^ (row_ & 7)) << 4);               \
            cp_async16(sa_ + off_, As_ + (size_t)row_ * DN + ch_ * 8);            \
            cp_async16(sB_ + off_, Bs_ + (size_t)row_ * DN + ch_ * 8);            \
        }                                                                         \
        asm volatile("cp.async.commit_group;" ::: "memory");                      \
    } while (0)

    ISSUE_CHUNK(0, 0);
    const int rA = lane & 15;
    const int chsel = lane >> 4;

    for (int it = 0; it < 12; it++) {
        if (it + 1 < 12) {
            ISSUE_CHUNK(it + 1, (it + 1) & 1);
            asm volatile("cp.async.wait_group 1;" ::: "memory");
        } else {
            asm volatile("cp.async.wait_group 0;" ::: "memory");
        }
        __syncthreads();
        {
            const int buf = it & 1;
            uint32_t sa = sb + buf * 16384;
            uint32_t sB = sb + 32768 + buf * 16384;
#pragma unroll
            for (int ks = 0; ks < 4; ks++) {
                uint32_t a[2][4];
#pragma unroll
                for (int mt = 0; mt < 2; mt++) {
                    int row = wm * 32 + mt * 16 + rA;
                    int ch = ks * 2 + chsel;
                    uint32_t addr = sa + row * 128 + ((ch ^ (row & 7)) << 4);
                    LDMX4(a[mt][0], a[mt][1], a[mt][2], a[mt][3], addr);
                }
#pragma unroll
                for (int ng = 0; ng < 4; ng++) {
                    uint32_t b0, b1, b2, b3;
                    int row = wn * 64 + ng * 16 + rA;
                    int ch = ks * 2 + chsel;
                    uint32_t addr = sB + row * 128 + ((ch ^ (row & 7)) << 4);
                    LDMX4(b0, b1, b2, b3, addr);
#pragma unroll
                    for (int mt = 0; mt < 2; mt++) {
                        mma16816(d[mt][ng * 2 + 0], a[mt], b0, b2);
                        mma16816(d[mt][ng * 2 + 1], a[mt], b1, b3);
                    }
                }
            }
        }
        __syncthreads();
    }
#undef ISSUE_CHUNK

    // epilogue: fp32 accum -> bf16 hi/lo
    size_t gb = (size_t)layer * totrows * DN;
    int r0 = (int)m0 + wm * 32 + (lane >> 2);
    int c0 = n0 + wn * 64 + (lane & 3) * 2;
#pragma unroll
    for (int mt = 0; mt < 2; mt++) {
#pragma unroll
        for (int ng = 0; ng < 8; ng++) {
            int row = r0 + mt * 16;
            int col = c0 + ng * 8;
#pragma unroll
            for (int half = 0; half < 2; half++) {
                float v0 = d[mt][ng][half * 2 + 0];
                float v1 = d[mt][ng][half * 2 + 1];
                size_t idx = gb + (size_t)(row + half * 8) * DN + col;
                __nv_bfloat16 h0 = __float2bfloat16(v0);
                __nv_bfloat16 h1 = __float2bfloat16(v1);
                __nv_bfloat16 l0 = __float2bfloat16(v0 - __bfloat162float(h0));
                __nv_bfloat16 l1 = __float2bfloat16(v1 - __bfloat162float(h1));
                *(__nv_bfloat162*)(g_Gh + idx) = __nv_bfloat162(h0, h1);
                *(__nv_bfloat162*)(g_Gl + idx) = __nv_bfloat162(l0, l1);
            }
        }
    }
}

// ---------------- S-phase: S = softmax(scale*(G Z^T + bias)) via mma ----------------
// grid (BM, ELN), 128 threads (4 warps)
template <int T>
__global__ __launch_bounds__(128) void sphase_kernel(int totrows) {
    constexpr int MT = (T + 15) / 16;
    constexpr int Tpad = MT * 16;
    constexpr int NT = MT;
    constexpr int SST = Tpad + 2;
    constexpr int AB = Tpad * 512;           // bytes per bf16 array [Tpad][256]
    constexpr int OFF_S = 4 * AB;
    constexpr int OFF_ZU = OFF_S + Tpad * SST * 4;
    constexpr int OFF_ZV = OFF_ZU + Tpad * 4;
    constexpr int OFF_U = OFF_ZV + Tpad * 4;
    constexpr int OFF_V = OFF_U + 1024;

    extern __shared__ __align__(128) char smem[];
    const uint32_t sb = smem_u32(smem);
    const int tid = threadIdx.x;
    const int lane = tid & 31;
    const int wid = tid >> 5;
    const int bm = blockIdx.x;
    const int layer = blockIdx.y;

    const __nv_bfloat16* srcs[4] = {
        g_Gh + ((size_t)layer * totrows + (size_t)bm * T) * DN,
        g_Gl + ((size_t)layer * totrows + (size_t)bm * T) * DN,
        g_zh + (size_t)bm * T * DN,
        g_zl + (size_t)bm * T * DN};
    // load T rows of each array, swizzled
#pragma unroll
    for (int a = 0; a < 4; a++) {
        for (int idx = tid; idx < T * 32; idx += 128) {
            int row = idx >> 5, ch = idx & 31;
            uint32_t off = (uint32_t)(a * AB) + row * 512 + ((ch ^ (row & 7)) << 4);
            cp_async16(sb + off, srcs[a] + (size_t)row * DN + ch * 8);
        }
    }
    asm volatile("cp.async.commit_group;" ::: "memory");
    // zero pad rows + stage u, v
    if constexpr (Tpad > T) {
        uint4 zz = make_uint4(0, 0, 0, 0);
        for (int idx = tid; idx < (Tpad - T) * 32; idx += 128) {
            int row = T + (idx >> 5), ch = idx & 31;
#pragma unroll
            for (int a = 0; a < 4; a++)
                *(uint4*)(smem + a * AB + row * 512 + ch * 16) = zz;
        }
    }
    {
        float* su_ = (float*)(smem + OFF_U);
        float* sv_ = (float*)(smem + OFF_V);
        for (int i = tid; i < DN; i += 128) {
            su_[i] = g_u[layer * DN + i];
            sv_[i] = g_v[layer * DN + i];
        }
    }
    asm volatile("cp.async.wait_group 0;" ::: "memory");
    __syncthreads();

    // zu/zv per row from (zh+zl)
    if (tid < T) {
        const float* su_ = (const float*)(smem + OFF_U);
        const float* sv_ = (const float*)(smem + OFF_V);
        int t = tid;
        float au = 0.f, av = 0.f;
#pragma unroll 4
        for (int ch = 0; ch < 32; ch++) {
            uint32_t offh = (uint32_t)(2 * AB) + t * 512 + ((ch ^ (t & 7)) << 4);
            const __nv_bfloat16* ph = (const __nv_bfloat16*)(smem + offh);
            const __nv_bfloat16* pl = (const __nv_bfloat16*)(smem + offh + AB);
#pragma unroll
            for (int j = 0; j < 8; j++) {
                float z = __bfloat162float(ph[j]) + __bfloat162float(pl[j]);
                au += z * su_[ch * 8 + j];
                av += z * sv_[ch * 8 + j];
            }
        }
        ((float*)(smem + OFF_ZU))[t] = au;
        ((float*)(smem + OFF_ZV))[t] = av;
    }

    // S tiles via mma (A = G rows, B = Z rows)
    float* sS = (float*)(smem + OFF_S);
    const int rA = lane & 15;
    const int chsel = lane >> 4;
    for (int tile = wid; tile < MT * NT; tile += 4) {
        int mi = tile / NT, nj = tile % NT;
        float d0[4] = {0.f, 0.f, 0.f, 0.f};
        float d1[4] = {0.f, 0.f, 0.f, 0.f};
#pragma unroll
        for (int kc = 0; kc < 16; kc++) {
            int ch = kc * 2 + chsel;
            int arow = mi * 16 + rA;
            uint32_t aaddr = sb + arow * 512 + ((ch ^ (arow & 7)) << 4);
            uint32_t ah[4], al[4];
            LDMX4(ah[0], ah[1], ah[2], ah[3], aaddr);
            LDMX4(al[0], al[1], al[2], al[3], aaddr + AB);
            int brow = nj * 16 + rA;
            uint32_t baddr = sb + 2 * AB + brow * 512 + ((ch ^ (brow & 7)) << 4);
            uint32_t bh0, bh1, bh2, bh3, bl0, bl1, bl2, bl3;
            LDMX4(bh0, bh1, bh2, bh3, baddr);
            LDMX4(bl0, bl1, bl2, bl3, baddr + AB);
            mma16816(d0, ah, bh0, bh2);
            mma16816(d1, ah, bh1, bh3);
            mma16816(d0, ah, bl0, bl2);
            mma16816(d1, ah, bl1, bl3);
            mma16816(d0, al, bh0, bh2);
            mma16816(d1, al, bh1, bh3);
        }
        int r = mi * 16 + (lane >> 2);
        int c = nj * 16 + (lane & 3) * 2;
        *(float2*)(sS + r * SST + c) = make_float2(d0[0], d0[1]);
        *(float2*)(sS + (r + 8) * SST + c) = make_float2(d0[2], d0[3]);
        *(float2*)(sS + r * SST + c + 8) = make_float2(d1[0], d1[1]);
        *(float2*)(sS + (r + 8) * SST + c + 8) = make_float2(d1[2], d1[3]);
    }
    __syncthreads();

    // softmax rows + bias
    const float* zu = (const float*)(smem + OFF_ZU);
    const float* zv = (const float*)(smem + OFF_ZV);
    float cterm = g_cc[layer];
    float* Sout = g_S + ((size_t)layer * BM + bm) * T * T;
    int e = lane;
    for (int l = wid; l < T; l += 4) {
        float zul = zu[l];
        bool v0 = (e < T);
        bool v1 = (T > 32) && (e + 32 < T);
        float x0 = v0 ? SCALE * (sS[l * SST + e] + zul + zv[e] + cterm) : -1e30f;
        float x1 = v1 ? SCALE * (sS[l * SST + e + 32] + zul + zv[e + 32] + cterm) : -1e30f;
        float mx = fmaxf(x0, x1);
#pragma unroll
        for (int o = 16; o; o >>= 1) mx = fmaxf(mx, __shfl_xor_sync(0xffffffffu, mx, o));
        float e0 = v0 ? __expf(x0 - mx) : 0.f;
        float e1 = v1 ? __expf(x1 - mx) : 0.f;
        float ssum = e0 + e1;
#pragma unroll
        for (int o = 16; o; o >>= 1) ssum += __shfl_xor_sync(0xffffffffu, ssum, o);
        float inv = 1.0f / ssum;
        if (v0) Sout[l * T + e] = e0 * inv;
        if (v1) Sout[l * T + e + 32] = e1 * inv;
    }
}

// ---------------- channel mean ----------------
template <int T>
__global__ __launch_bounds__(256) void mean_kernel() {
    constexpr int TT = T * T;
    int b = blockIdx.x, layer = blockIdx.y;
    const float* Sb = g_S + ((size_t)layer * BM + (size_t)b * MN) * TT;
    float* Ab = g_A + ((size_t)layer * BN + b) * TT;
    for (int r = threadIdx.x; r < TT; r += blockDim.x) {
        float s = 0.f;
#pragma unroll 5
        for (int m = 0; m < MN; m++) s += Sb[(size_t)m * TT + r];
        Ab[r] = s * (1.0f / MN);
    }
}

// ---------------- expand (repeat / tile) ----------------
template <int T, int P, bool TILE>
__global__ __launch_bounds__(256) void expand_kernel(float* __restrict__ out) {
    __shared__ float sA[T * T];
    int b = blockIdx.x, layer = blockIdx.y;
    const float* Ab = g_A + ((size_t)layer * BN + b) * T * T;
    for (int i = threadIdx.x; i < T * T; i += 256) sA[i] = Ab[i];
    __syncthreads();
    float* ob = out + ((size_t)layer * BN + b) * LL;
    for (int i = threadIdx.x; i < LL; i += 256) {
        int l = i / LN, s = i - l * LN;
        int al = TILE ? (l % P) : (l / P);
        int as = TILE ? (s % P) : (s / P);
        ob[i] = sA[al * T + as];
    }
}

// ---------------- host orchestration ----------------
template <int T>
static constexpr int sphase_smem() {
    constexpr int MT = (T + 15) / 16;
    constexpr int Tpad = MT * 16;
    constexpr int SST = Tpad + 2;
    return 4 * Tpad * 512 + Tpad * SST * 4 + 2 * Tpad * 4 + 2048;
}

template <int T, int C, int P, bool TILE>
static void run_branch(const float* w, float* outbase) {
    wtrans_kernel<<<(DN * C * 3 + 255) / 256, 256>>>(w, C);
    conv_embed_kernel<T, C><<<BM, 256>>>();
    int totrows = BM * T;
    gemm_kernel<<<dim3(6, totrows / 128), 256, GEMM_SMEM>>>(totrows);
    constexpr int smem = sphase_smem<T>();
    cudaFuncSetAttribute(sphase_kernel<T>, cudaFuncAttributeMaxDynamicSharedMemorySize, smem);
    sphase_kernel<T><<<dim3(BM, ELN), 128, smem>>>(totrows);
    mean_kernel<T><<<dim3(BN, ELN), 256>>>();
    expand_kernel<T, P, TILE><<<dim3(BN, ELN), 256>>>(outbase);
}

extern "C" void kernel_launch(void* const* d_in, const int* in_sizes, int n_in,
                              void* d_out, int out_size) {
    const float* x = (const float*)d_in[0];
    const float* Wq = (const float*)d_in[7];
    const float* bq = (const float*)d_in[8];
    const float* Wk = (const float*)d_in[9];
    const float* bk = (const float*)d_in[10];
    float* out = (float*)d_out;

    cudaFuncSetAttribute(gemm_kernel, cudaFuncAttributeMaxDynamicSharedMemorySize, GEMM_SMEM);

    revin_kernel<<<BN, 256>>>(x);
    meff_kernel<<<dim3(16, 16, ELN), dim3(16, 16)>>>(Wq, Wk);
    meffT_kernel<<<dim3(256, ELN), 256>>>();
    uvc_kernel<<<dim3(ELN, 32), 256>>>(Wq, Wk, bq, bk);

    run_branch<35, 3, 3, false>((const float*)d_in[1], out + (size_t)0 * BN * LL);
    run_branch<3, 35, 3, true>((const float*)d_in[2], out + (size_t)9 * BN * LL);

    run_branch<21, 5, 5, false>((const float*)d_in[3], out + (size_t)3 * BN * LL);
    run_branch<5, 21, 5, true>((const float*)d_in[4], out + (size_t)12 * BN * LL);

    run_branch<15, 7, 7, false>((const float*)d_in[5], out + (size_t)6 * BN * LL);
    run_branch<7, 15, 7, true>((const float*)d_in[6], out + (size_t)15 * BN * LL);
}

// round 5
// speedup vs baseline: 2.8690x; 1.0764x over previous
#include <cuda_runtime.h>
#include <cuda_bf16.h>
#include <math.h>
#include <cstdint>

#define BN 128
#define LN 105
#define MN 55
#define DN 256
#define ELN 3
static constexpr int BM = BN * MN;      // 7040
static constexpr int LL = LN * LN;      // 11025
static constexpr float SCALE = 0.0625f; // 1/sqrt(256)

// ---------------- scratch (device globals) ----------------
__device__ __align__(128) float g_xt[BM * LN];
__device__ __align__(128) __nv_bfloat16 g_zh[(size_t)BM * 35 * DN];
__device__ __align__(128) __nv_bfloat16 g_zl[(size_t)BM * 35 * DN];
__device__ __align__(128) float g_wT[3 * 35 * DN];
__device__ __align__(128) float g_meff[ELN * DN * DN];
__device__ __align__(128) __nv_bfloat16 g_mth[ELN * DN * DN];  // MeffT hi [n][k]
__device__ __align__(128) __nv_bfloat16 g_mtl[ELN * DN * DN];  // MeffT lo
__device__ float g_u[ELN * DN];
__device__ float g_v[ELN * DN];
__device__ float g_cc[ELN];
__device__ __align__(128) float g_S[(size_t)ELN * BM * 35 * 35];

// ---------------- helpers ----------------
__device__ __forceinline__ uint32_t smem_u32(const void* p) {
    uint32_t a;
    asm("{ .reg .u64 t; cvta.to.shared.u64 t, %1; cvt.u32.u64 %0, t; }" : "=r"(a) : "l"(p));
    return a;
}
__device__ __forceinline__ void cp_async16(uint32_t saddr, const void* gptr) {
    asm volatile("cp.async.ca.shared.global [%0], [%1], 16;" :: "r"(saddr), "l"(gptr) : "memory");
}
__device__ __forceinline__ void mma16816(float* d, const uint32_t* a, uint32_t b0, uint32_t b1) {
    asm volatile(
        "mma.sync.aligned.m16n8k16.row.col.f32.bf16.bf16.f32 "
        "{%0,%1,%2,%3}, {%4,%5,%6,%7}, {%8,%9}, {%0,%1,%2,%3};"
        : "+f"(d[0]), "+f"(d[1]), "+f"(d[2]), "+f"(d[3])
        : "r"(a[0]), "r"(a[1]), "r"(a[2]), "r"(a[3]), "r"(b0), "r"(b1));
}
#define LDMX4(r0, r1, r2, r3, addr) \
    asm volatile("ldmatrix.sync.aligned.m8n8.x4.shared.b16 {%0,%1,%2,%3}, [%4];" \
        : "=r"(r0), "=r"(r1), "=r"(r2), "=r"(r3) : "r"(addr))

// ---------------- RevIN + transpose ----------------
__global__ void revin_kernel(const float* __restrict__ x) {
    __shared__ float sx[LN * MN];
    __shared__ float smean[MN], sinv[MN];
    int b = blockIdx.x;
    const float* xb = x + (size_t)b * LN * MN;
    for (int i = threadIdx.x; i < LN * MN; i += blockDim.x) sx[i] = xb[i];
    __syncthreads();
    for (int m = threadIdx.x; m < MN; m += blockDim.x) {
        float s = 0.f, s2 = 0.f;
        for (int l = 0; l < LN; l++) { float v = sx[l * MN + m]; s += v; s2 += v * v; }
        float mean = s * (1.0f / LN);
        float var = s2 * (1.0f / LN) - mean * mean;
        smean[m] = mean;
        sinv[m] = rsqrtf(var + 1e-5f);
    }
    __syncthreads();
    float* ob = g_xt + (size_t)b * MN * LN;
    for (int i = threadIdx.x; i < MN * LN; i += blockDim.x) {
        int m = i / LN, l = i - m * LN;
        ob[i] = (sx[l * MN + m] - smean[m]) * sinv[m];
    }
}

// ---------------- Meff = Wq @ Wk^T ----------------
__global__ void meff_kernel(const float* __restrict__ Wq, const float* __restrict__ Wk) {
    int l = blockIdx.z;
    int i0 = blockIdx.y * 16, j0 = blockIdx.x * 16;
    __shared__ float sq[16][17], sk[16][17];
    int ty = threadIdx.y, tx = threadIdx.x;
    float acc = 0.f;
    const float* wq = Wq + (size_t)l * DN * DN;
    const float* wk = Wk + (size_t)l * DN * DN;
    for (int k0 = 0; k0 < DN; k0 += 16) {
        sq[ty][tx] = wq[(i0 + ty) * DN + k0 + tx];
        sk[ty][tx] = wk[(j0 + ty) * DN + k0 + tx];
        __syncthreads();
#pragma unroll
        for (int kk = 0; kk < 16; kk++) acc += sq[ty][kk] * sk[tx][kk];
        __syncthreads();
    }
    g_meff[(size_t)l * DN * DN + (i0 + ty) * DN + j0 + tx] = acc;
}

__global__ void meffT_kernel() {
    int l = blockIdx.y;
    int i = blockIdx.x * 256 + threadIdx.x;   // n*256+k
    int n = i >> 8, k = i & 255;
    float v = g_meff[(size_t)l * DN * DN + k * DN + n];
    __nv_bfloat16 h = __float2bfloat16(v);
    g_mth[(size_t)l * DN * DN + i] = h;
    g_mtl[(size_t)l * DN * DN + i] = __float2bfloat16(v - __bfloat162float(h));
}

__global__ void uvc_kernel(const float* __restrict__ Wq, const float* __restrict__ Wk,
                           const float* __restrict__ bq, const float* __restrict__ bk) {
    int l = blockIdx.x;
    int wid = threadIdx.x >> 5, lane = threadIdx.x & 31;
    int k = blockIdx.y * 8 + wid;
    float su = 0.f, sv = 0.f;
    const float* wq = Wq + (size_t)l * DN * DN + (size_t)k * DN;
    const float* wk = Wk + (size_t)l * DN * DN + (size_t)k * DN;
    for (int d = lane; d < DN; d += 32) {
        su += wq[d] * bk[l * DN + d];
        sv += wk[d] * bq[l * DN + d];
    }
#pragma unroll
    for (int o = 16; o; o >>= 1) {
        su += __shfl_xor_sync(0xffffffffu, su, o);
        sv += __shfl_xor_sync(0xffffffffu, sv, o);
    }
    if (lane == 0) {
        g_u[l * DN + k] = su;
        g_v[l * DN + k] = sv;
    }
    if (blockIdx.y == 0 && wid == 0) {
        float c = 0.f;
        for (int d = lane; d < DN; d += 32) c += bq[l * DN + d] * bk[l * DN + d];
#pragma unroll
        for (int o = 16; o; o >>= 1) c += __shfl_xor_sync(0xffffffffu, c, o);
        if (lane == 0) g_cc[l] = c;
    }
}

// ---------------- conv weight transpose ----------------
__global__ void wtrans_kernel(const float* __restrict__ w, int C) {
    int i = blockIdx.x * blockDim.x + threadIdx.x;
    int tot = DN * C * 3;
    if (i < tot) {
        int d = i / (C * 3);
        int r = i - d * (C * 3);
        g_wT[r * DN + d] = w[i];
    }
}

// ---------------- circular conv + PE -> Z (bf16 hi/lo) ----------------
template <int T, int C>
__global__ __launch_bounds__(256) void conv_embed_kernel() {
    constexpr int CHUNK = 8;
    __shared__ float sx[LN];
    __shared__ float sw[3 * CHUNK * DN];
    int bm = blockIdx.x;
    int d = threadIdx.x;
    for (int i = threadIdx.x; i < LN; i += blockDim.x) sx[i] = g_xt[(size_t)bm * LN + i];
    float acc[T];
#pragma unroll
    for (int t = 0; t < T; t++) acc[t] = 0.f;
    for (int c0 = 0; c0 < C; c0 += CHUNK) {
        int cw = (C - c0 < CHUNK) ? (C - c0) : CHUNK;
        __syncthreads();
        for (int i = threadIdx.x; i < cw * 3 * DN; i += blockDim.x)
            sw[i] = g_wT[c0 * 3 * DN + i];
        __syncthreads();
        for (int ci = 0; ci < cw; ci++) {
            int c = c0 + ci;
            float w0 = sw[(ci * 3 + 0) * DN + d];
            float w1 = sw[(ci * 3 + 1) * DN + d];
            float w2 = sw[(ci * 3 + 2) * DN + d];
#pragma unroll
            for (int t = 0; t < T; t++) {
                int tm = (t == 0) ? (T - 1) : (t - 1);
                int tp = (t == T - 1) ? 0 : (t + 1);
                acc[t] += w0 * sx[tm * C + c] + w1 * sx[t * C + c] + w2 * sx[tp * C + c];
            }
        }
    }
    float freq = expf(-(float)(2 * (d >> 1)) * (9.210340371976184f / 256.f));
    bool isodd = (d & 1);
#pragma unroll
    for (int t = 0; t < T; t++) {
        float arg = (float)t * freq;
        float pe = isodd ? cosf(arg) : sinf(arg);
        float zv = acc[t] + pe;
        size_t ridx = ((size_t)bm * T + t) * DN + d;
        __nv_bfloat16 h = __float2bfloat16(zv);
        g_zh[ridx] = h;
        g_zl[ridx] = __float2bfloat16(zv - __bfloat162float(h));
    }
}

// ---------------- fused: G = Z@Meff, S = softmax(scale*(G Z^T + bias)) ----------------
// smem layout (dynamic, bytes):
static constexpr int OZH = 0;         // Zh [128][256] bf16 swizzled (65536)
static constexpr int OZL = 65536;     // Zl
static constexpr int OGH = 131072;    // Gh half [128][128] bf16 (32768)
static constexpr int OGL = 163840;    // Gl half
static constexpr int OBH = 196608;    // Bh chunk [128 n][64 k] (16384)
static constexpr int OBL = 212992;    // Bl chunk
static constexpr int OSS = 196608;    // S overlay (reuses B region, <= 32KB)
static constexpr int OU  = 229376;    // u (1024)
static constexpr int OV  = 230400;    // v (1024)
static constexpr int OZU = 231424;    // zu (512)
static constexpr int OZV = 231936;    // zv (512)
static constexpr int FUSED_SMEM = 232448;

template <int T>
__global__ __launch_bounds__(512, 1) void fused_kernel() {
    constexpr int MT = (T + 15) / 16;
    constexpr int QB = (T < 16) ? (16 / T) : 1;
    constexpr int NB = (T < 16) ? (8 * QB) : (128 / T);
    constexpr int NTILES = (T < 16) ? 8 : (NB * MT * MT);
    constexpr int TC = (T + 3) & ~3;
    constexpr int SLOTS = (NTILES + 15) / 16;

    extern __shared__ __align__(128) char smem[];
    const uint32_t sb = smem_u32(smem);
    const int tid = threadIdx.x;
    const int lane = tid & 31;
    const int wid = tid >> 5;
    const int layer = blockIdx.y;
    const int bm0 = blockIdx.x * NB;
    const int nbm = min(NB, BM - bm0);
    const int nrows = nbm * T;

    // ---- load Z rows, zero pad rows, load u/v ----
    const __nv_bfloat16* Zh = g_zh + (size_t)bm0 * T * DN;
    const __nv_bfloat16* Zl = g_zl + (size_t)bm0 * T * DN;
    for (int idx = tid; idx < nrows * 32; idx += 512) {
        int r = idx >> 5, c = idx & 31;
        uint32_t off = r * 512 + ((c ^ (r & 7)) << 4);
        cp_async16(sb + OZH + off, Zh + (size_t)r * DN + c * 8);
        cp_async16(sb + OZL + off, Zl + (size_t)r * DN + c * 8);
    }
    asm volatile("cp.async.commit_group;" ::: "memory");
    for (int idx = tid + nrows * 32; idx < 128 * 32; idx += 512) {
        int r = idx >> 5, c = idx & 31;
        uint32_t off = r * 512 + (c << 4);  // zeros: position within row irrelevant
        *(uint4*)(smem + OZH + off) = make_uint4(0, 0, 0, 0);
        *(uint4*)(smem + OZL + off) = make_uint4(0, 0, 0, 0);
    }
    if (tid < DN) ((float*)(smem + OU))[tid] = g_u[layer * DN + tid];
    else if (tid < 2 * DN) ((float*)(smem + OV))[tid - DN] = g_v[layer * DN + tid - DN];
    asm volatile("cp.async.wait_group 0;" ::: "memory");
    __syncthreads();

    // ---- zu/zv per row (4 threads per row) ----
    {
        int r = tid >> 2, p = tid & 3;
        float au = 0.f, av = 0.f;
        if (r < nrows) {
            const float* su = (const float*)(smem + OU);
            const float* sv = (const float*)(smem + OV);
            for (int c = p * 8; c < p * 8 + 8; c++) {
                uint32_t off = r * 512 + ((c ^ (r & 7)) << 4);
                const __nv_bfloat16* ph = (const __nv_bfloat16*)(smem + OZH + off);
                const __nv_bfloat16* pl = (const __nv_bfloat16*)(smem + OZL + off);
#pragma unroll
                for (int j = 0; j < 8; j++) {
                    float z = __bfloat162float(ph[j]) + __bfloat162float(pl[j]);
                    au += z * su[c * 8 + j];
                    av += z * sv[c * 8 + j];
                }
            }
        }
        au += __shfl_xor_sync(0xffffffffu, au, 1);
        au += __shfl_xor_sync(0xffffffffu, au, 2);
        av += __shfl_xor_sync(0xffffffffu, av, 1);
        av += __shfl_xor_sync(0xffffffffu, av, 2);
        if (p == 0 && r < nrows) {
            ((float*)(smem + OZU))[r] = au;
            ((float*)(smem + OZV))[r] = av;
        }
    }

    const int wm = wid >> 2, wn = wid & 3;
    const int rA = lane & 15;
    const int chsel = lane >> 4;

    float sfr[SLOTS][2][4];
#pragma unroll
    for (int s = 0; s < SLOTS; s++)
#pragma unroll
        for (int j = 0; j < 2; j++)
#pragma unroll
            for (int q = 0; q < 4; q++) sfr[s][j][q] = 0.f;

    const __nv_bfloat16* Bh_src = g_mth + (size_t)layer * DN * DN;
    const __nv_bfloat16* Bl_src = g_mtl + (size_t)layer * DN * DN;
    const int br0 = tid >> 3, bc0 = tid & 7;
    const int br1 = (tid + 512) >> 3, bc1 = (tid + 512) & 7;
    const uint32_t bo0 = br0 * 128 + ((bc0 ^ (br0 & 7)) << 4);
    const uint32_t bo1 = br1 * 128 + ((bc1 ^ (br1 & 7)) << 4);

    for (int h = 0; h < 2; h++) {
        float acc[2][4][4];
#pragma unroll
        for (int mt = 0; mt < 2; mt++)
#pragma unroll
            for (int j = 0; j < 4; j++)
#pragma unroll
                for (int q = 0; q < 4; q++) acc[mt][j][q] = 0.f;

        uint4 pre0, pre1, pre2, pre3;
        {
            const __nv_bfloat16* bh = Bh_src + (size_t)(h * 128) * DN;
            const __nv_bfloat16* bl = Bl_src + (size_t)(h * 128) * DN;
            pre0 = *(const uint4*)(bh + (size_t)br0 * DN + bc0 * 8);
            pre1 = *(const uint4*)(bh + (size_t)br1 * DN + bc1 * 8);
            pre2 = *(const uint4*)(bl + (size_t)br0 * DN + bc0 * 8);
            pre3 = *(const uint4*)(bl + (size_t)br1 * DN + bc1 * 8);
        }
        for (int kc = 0; kc < 4; kc++) {
            __syncthreads();
            *(uint4*)(smem + OBH + bo0) = pre0;
            *(uint4*)(smem + OBH + bo1) = pre1;
            *(uint4*)(smem + OBL + bo0) = pre2;
            *(uint4*)(smem + OBL + bo1) = pre3;
            __syncthreads();
            if (kc < 3) {
                const __nv_bfloat16* bh = Bh_src + (size_t)(h * 128) * DN + (kc + 1) * 64;
                const __nv_bfloat16* bl = Bl_src + (size_t)(h * 128) * DN + (kc + 1) * 64;
                pre0 = *(const uint4*)(bh + (size_t)br0 * DN + bc0 * 8);
                pre1 = *(const uint4*)(bh + (size_t)br1 * DN + bc1 * 8);
                pre2 = *(const uint4*)(bl + (size_t)br0 * DN + bc0 * 8);
                pre3 = *(const uint4*)(bl + (size_t)br1 * DN + bc1 * 8);
            }
#pragma unroll
            for (int ks = 0; ks < 4; ks++) {
                int chA = kc * 8 + ks * 2 + chsel;
                uint32_t ah[2][4], al[2][4];
#pragma unroll
                for (int mt = 0; mt < 2; mt++) {
                    int row = wm * 32 + mt * 16 + rA;
                    uint32_t ad = sb + OZH + row * 512 + ((chA ^ (row & 7)) << 4);
                    LDMX4(ah[mt][0], ah[mt][1], ah[mt][2], ah[mt][3], ad);
                    LDMX4(al[mt][0], al[mt][1], al[mt][2], al[mt][3], ad + 65536);
                }
                uint32_t bh[2][4], bl[2][4];
#pragma unroll
                for (int ng = 0; ng < 2; ng++) {
                    int row = wn * 32 + ng * 16 + rA;
                    uint32_t bd = sb + OBH + row * 128 + (((ks * 2 + chsel) ^ (row & 7)) << 4);
                    LDMX4(bh[ng][0], bh[ng][1], bh[ng][2], bh[ng][3], bd);
                    LDMX4(bl[ng][0], bl[ng][1], bl[ng][2], bl[ng][3], bd + 16384);
                }
#pragma unroll
                for (int mt = 0; mt < 2; mt++)
#pragma unroll
                    for (int ng = 0; ng < 2; ng++) {
                        mma16816(acc[mt][ng * 2 + 0], ah[mt], bh[ng][0], bh[ng][2]);
                        mma16816(acc[mt][ng * 2 + 1], ah[mt], bh[ng][1], bh[ng][3]);
                        mma16816(acc[mt][ng * 2 + 0], ah[mt], bl[ng][0], bl[ng][2]);
                        mma16816(acc[mt][ng * 2 + 1], ah[mt], bl[ng][1], bl[ng][3]);
                        mma16816(acc[mt][ng * 2 + 0], al[mt], bh[ng][0], bh[ng][2]);
                        mma16816(acc[mt][ng * 2 + 1], al[mt], bh[ng][1], bh[ng][3]);
                    }
            }
        }
        __syncthreads();
        // G accum -> bf16 hi/lo smem
#pragma unroll
        for (int mt = 0; mt < 2; mt++)
#pragma unroll
            for (int j = 0; j < 4; j++) {
                int c = wn * 32 + (j >> 1) * 16 + (j & 1) * 8 + (lane & 3) * 2;
#pragma unroll
                for (int half = 0; half < 2; half++) {
                    int r = wm * 32 + mt * 16 + (lane >> 2) + half * 8;
                    float v0 = acc[mt][j][half * 2 + 0];
                    float v1 = acc[mt][j][half * 2 + 1];
                    uint32_t off = r * 256 + ((((c >> 3)) ^ (r & 7)) << 4) + (c & 7) * 2;
                    __nv_bfloat16 h0 = __float2bfloat16(v0);
                    __nv_bfloat16 h1 = __float2bfloat16(v1);
                    *(__nv_bfloat162*)(smem + OGH + off) = __nv_bfloat162(h0, h1);
                    __nv_bfloat16 l0 = __float2bfloat16(v0 - __bfloat162float(h0));
                    __nv_bfloat16 l1 = __float2bfloat16(v1 - __bfloat162float(h1));
                    *(__nv_bfloat162*)(smem + OGL + off) = __nv_bfloat162(l0, l1);
                }
            }
        __syncthreads();
        // phase2: S += G_half @ Z_half^T on diagonal tiles
        int slot = 0;
        for (int t = wid; t < NTILES; t += 16, slot++) {
            int rb, cb;
            if (T < 16) {
                rb = cb = t * QB * T;
            } else {
                int tbm = t / (MT * MT);
                int rem = t % (MT * MT);
                rb = tbm * T + (rem / MT) * 16;
                cb = tbm * T + (rem % MT) * 16;
            }
#pragma unroll
            for (int kc = 0; kc < 8; kc++) {
                int ch = kc * 2 + chsel;
                int arow = rb + rA;
                uint32_t aad = sb + OGH + arow * 256 + ((ch ^ (arow & 7)) << 4);
                uint32_t gh[4], gl[4];
                LDMX4(gh[0], gh[1], gh[2], gh[3], aad);
                LDMX4(gl[0], gl[1], gl[2], gl[3], aad + 32768);
                int brow = cb + rA;
                int chz = h * 16 + ch;
                uint32_t bad = sb + OZH + brow * 512 + ((chz ^ (brow & 7)) << 4);
                uint32_t zh2[4], zl2[4];
                LDMX4(zh2[0], zh2[1], zh2[2], zh2[3], bad);
                LDMX4(zl2[0], zl2[1], zl2[2], zl2[3], bad + 65536);
                mma16816(sfr[slot][0], gh, zh2[0], zh2[2]);
                mma16816(sfr[slot][1], gh, zh2[1], zh2[3]);
                mma16816(sfr[slot][0], gh, zl2[0], zl2[2]);
                mma16816(sfr[slot][1], gh, zl2[1], zl2[3]);
                mma16816(sfr[slot][0], gl, zh2[0], zh2[2]);
                mma16816(sfr[slot][1], gl, zh2[1], zh2[3]);
            }
        }
    }
    __syncthreads();

    // ---- S frags -> smem overlay ----
    float* sS = (float*)(smem + OSS);
    {
        int slot = 0;
        for (int t = wid; t < NTILES; t += 16, slot++) {
            int tbm = -1, ti = 0, tj = 0;
            if (T >= 16) {
                tbm = t / (MT * MT);
                int rem = t % (MT * MT);
                ti = rem / MT;
                tj = rem % MT;
            }
            int fr = lane >> 2, fc = (lane & 3) * 2;
#pragma unroll
            for (int j = 0; j < 2; j++)
#pragma unroll
                for (int q = 0; q < 4; q++) {
                    int rr = fr + (q >> 1) * 8;
                    int cc = fc + (q & 1) + j * 8;
                    float v = sfr[slot][j][q];
                    if (T < 16) {
                        int qr = rr / T, qc = cc / T;
                        if (qr == qc && qr < QB) {
                            int bm = t * QB + qr;
                            if (bm < nbm) sS[(bm * T + rr - qr * T) * TC + (cc - qc * T)] = v;
                        }
                    } else {
                        if (tbm < nbm && ti * 16 + rr < T && tj * 16 + cc < T)
                            sS[(tbm * T + ti * 16 + rr) * TC + tj * 16 + cc] = v;
                    }
                }
        }
    }
    __syncthreads();

    // ---- softmax rows -> g_S ----
    float cterm = g_cc[layer];
    const float* zu = (const float*)(smem + OZU);
    const float* zv = (const float*)(smem + OZV);
    int e = lane;
    for (int rho = wid; rho < nrows; rho += 16) {
        int bm = rho / T, l = rho % T;
        const float* row = sS + (bm * T + l) * TC;
        bool v0 = (e < T);
        bool v1 = (T > 32) && (e + 32 < T);
        float zul = zu[rho];
        float x0 = v0 ? SCALE * (row[e] + zul + zv[bm * T + e] + cterm) : -1e30f;
        float x1 = v1 ? SCALE * (row[e + 32] + zul + zv[bm * T + e + 32] + cterm) : -1e30f;
        float mx = fmaxf(x0, x1);
#pragma unroll
        for (int o = 16; o; o >>= 1) mx = fmaxf(mx, __shfl_xor_sync(0xffffffffu, mx, o));
        float e0 = v0 ? __expf(x0 - mx) : 0.f;
        float e1 = v1 ? __expf(x1 - mx) : 0.f;
        float ssum = e0 + e1;
#pragma unroll
        for (int o = 16; o; o >>= 1) ssum += __shfl_xor_sync(0xffffffffu, ssum, o);
        float inv = 1.0f / ssum;
        float* So = g_S + ((size_t)layer * BM + bm0 + bm) * T * T + (size_t)l * T;
        if (v0) So[e] = e0 * inv;
        if (v1) So[e + 32] = e1 * inv;
    }
}

// ---------------- channel mean + expand (fused) ----------------
template <int T, int P, bool TILE>
__global__ __launch_bounds__(256) void mean_expand_kernel(float* __restrict__ out) {
    constexpr int TT = T * T;
    __shared__ float sA[TT];
    int b = blockIdx.x, layer = blockIdx.y;
    const float* Sb = g_S + ((size_t)layer * BM + (size_t)b * MN) * TT;
    for (int r = threadIdx.x; r < TT; r += 256) {
        float s = 0.f;
#pragma unroll 5
        for (int m = 0; m < MN; m++) s += Sb[(size_t)m * TT + r];
        sA[r] = s * (1.0f / MN);
    }
    __syncthreads();
    float* ob = out + ((size_t)layer * BN + b) * LL;
    for (int i = threadIdx.x; i < LL; i += 256) {
        int l = i / LN, s = i - l * LN;
        int al = TILE ? (l % P) : (l / P);
        int as = TILE ? (s % P) : (s / P);
        ob[i] = sA[al * T + as];
    }
}

// ---------------- host orchestration ----------------
template <int T, int C, int P, bool TILE>
static void run_branch(const float* w, float* outbase) {
    wtrans_kernel<<<(DN * C * 3 + 255) / 256, 256>>>(w, C);
    conv_embed_kernel<T, C><<<BM, 256>>>();
    constexpr int QB = (T < 16) ? (16 / T) : 1;
    constexpr int NB = (T < 16) ? (8 * QB) : (128 / T);
    int nblk = (BM + NB - 1) / NB;
    cudaFuncSetAttribute(fused_kernel<T>, cudaFuncAttributeMaxDynamicSharedMemorySize, FUSED_SMEM);
    fused_kernel<T><<<dim3(nblk, ELN), 512, FUSED_SMEM>>>();
    mean_expand_kernel<T, P, TILE><<<dim3(BN, ELN), 256>>>(outbase);
}

extern "C" void kernel_launch(void* const* d_in, const int* in_sizes, int n_in,
                              void* d_out, int out_size) {
    const float* x = (const float*)d_in[0];
    const float* Wq = (const float*)d_in[7];
    const float* bq = (const float*)d_in[8];
    const float* Wk = (const float*)d_in[9];
    const float* bk = (const float*)d_in[10];
    float* out = (float*)d_out;

    revin_kernel<<<BN, 256>>>(x);
    meff_kernel<<<dim3(16, 16, ELN), dim3(16, 16)>>>(Wq, Wk);
    meffT_kernel<<<dim3(256, ELN), 256>>>();
    uvc_kernel<<<dim3(ELN, 32), 256>>>(Wq, Wk, bq, bk);

    run_branch<35, 3, 3, false>((const float*)d_in[1], out + (size_t)0 * BN * LL);
    run_branch<3, 35, 3, true>((const float*)d_in[2], out + (size_t)9 * BN * LL);

    run_branch<21, 5, 5, false>((const float*)d_in[3], out + (size_t)3 * BN * LL);
    run_branch<5, 21, 5, true>((const float*)d_in[4], out + (size_t)12 * BN * LL);

    run_branch<15, 7, 7, false>((const float*)d_in[5], out + (size_t)6 * BN * LL);
    run_branch<7, 15, 7, true>((const float*)d_in[6], out + (size_t)15 * BN * LL);
}

// round 6
// speedup vs baseline: 2.9107x; 1.0145x over previous
#include <cuda_runtime.h>
#include <cuda_bf16.h>
#include <math.h>
#include <cstdint>

#define BN 128
#define LN 105
#define MN 55
#define DN 256
#define ELN 3
static constexpr int BM = BN * MN;      // 7040
static constexpr int LL = LN * LN;      // 11025
static constexpr float SCALE = 0.0625f; // 1/sqrt(256)

// ---------------- scratch (device globals) ----------------
__device__ __align__(128) float g_xt[BM * LN];
__device__ __align__(128) __nv_bfloat16 g_zh[(size_t)BM * 35 * DN];
__device__ __align__(128) __nv_bfloat16 g_zl[(size_t)BM * 35 * DN];
__device__ __align__(128) float g_wT[3 * 35 * DN];
__device__ __align__(128) float g_meff[ELN * DN * DN];
__device__ __align__(128) __nv_bfloat16 g_mth[ELN * DN * DN];  // MeffT hi [n][k]
__device__ __align__(128) __nv_bfloat16 g_mtl[ELN * DN * DN];  // MeffT lo
__device__ float g_u[ELN * DN];
__device__ float g_v[ELN * DN];
__device__ float g_cc[ELN];
__device__ __align__(128) float g_S[(size_t)ELN * BM * 35 * 35];

// ---------------- helpers ----------------
__device__ __forceinline__ uint32_t smem_u32(const void* p) {
    uint32_t a;
    asm("{ .reg .u64 t; cvta.to.shared.u64 t, %1; cvt.u32.u64 %0, t; }" : "=r"(a) : "l"(p));
    return a;
}
__device__ __forceinline__ void cp_async16(uint32_t saddr, const void* gptr) {
    asm volatile("cp.async.ca.shared.global [%0], [%1], 16;" :: "r"(saddr), "l"(gptr) : "memory");
}
__device__ __forceinline__ void mma16816(float* d, const uint32_t* a, uint32_t b0, uint32_t b1) {
    asm volatile(
        "mma.sync.aligned.m16n8k16.row.col.f32.bf16.bf16.f32 "
        "{%0,%1,%2,%3}, {%4,%5,%6,%7}, {%8,%9}, {%0,%1,%2,%3};"
        : "+f"(d[0]), "+f"(d[1]), "+f"(d[2]), "+f"(d[3])
        : "r"(a[0]), "r"(a[1]), "r"(a[2]), "r"(a[3]), "r"(b0), "r"(b1));
}
#define LDMX4(r0, r1, r2, r3, addr) \
    asm volatile("ldmatrix.sync.aligned.m8n8.x4.shared.b16 {%0,%1,%2,%3}, [%4];" \
        : "=r"(r0), "=r"(r1), "=r"(r2), "=r"(r3) : "r"(addr))

// ---------------- RevIN + transpose ----------------
__global__ void revin_kernel(const float* __restrict__ x) {
    __shared__ float sx[LN * MN];
    __shared__ float smean[MN], sinv[MN];
    int b = blockIdx.x;
    const float* xb = x + (size_t)b * LN * MN;
    for (int i = threadIdx.x; i < LN * MN; i += blockDim.x) sx[i] = xb[i];
    __syncthreads();
    for (int m = threadIdx.x; m < MN; m += blockDim.x) {
        float s = 0.f, s2 = 0.f;
        for (int l = 0; l < LN; l++) { float v = sx[l * MN + m]; s += v; s2 += v * v; }
        float mean = s * (1.0f / LN);
        float var = s2 * (1.0f / LN) - mean * mean;
        smean[m] = mean;
        sinv[m] = rsqrtf(var + 1e-5f);
    }
    __syncthreads();
    float* ob = g_xt + (size_t)b * MN * LN;
    for (int i = threadIdx.x; i < MN * LN; i += blockDim.x) {
        int m = i / LN, l = i - m * LN;
        ob[i] = (sx[l * MN + m] - smean[m]) * sinv[m];
    }
}

// ---------------- Meff = Wq @ Wk^T ----------------
__global__ void meff_kernel(const float* __restrict__ Wq, const float* __restrict__ Wk) {
    int l = blockIdx.z;
    int i0 = blockIdx.y * 16, j0 = blockIdx.x * 16;
    __shared__ float sq[16][17], sk[16][17];
    int ty = threadIdx.y, tx = threadIdx.x;
    float acc = 0.f;
    const float* wq = Wq + (size_t)l * DN * DN;
    const float* wk = Wk + (size_t)l * DN * DN;
    for (int k0 = 0; k0 < DN; k0 += 16) {
        sq[ty][tx] = wq[(i0 + ty) * DN + k0 + tx];
        sk[ty][tx] = wk[(j0 + ty) * DN + k0 + tx];
        __syncthreads();
#pragma unroll
        for (int kk = 0; kk < 16; kk++) acc += sq[ty][kk] * sk[tx][kk];
        __syncthreads();
    }
    g_meff[(size_t)l * DN * DN + (i0 + ty) * DN + j0 + tx] = acc;
}

__global__ void meffT_kernel() {
    int l = blockIdx.y;
    int i = blockIdx.x * 256 + threadIdx.x;   // n*256+k
    int n = i >> 8, k = i & 255;
    float v = g_meff[(size_t)l * DN * DN + k * DN + n];
    __nv_bfloat16 h = __float2bfloat16(v);
    g_mth[(size_t)l * DN * DN + i] = h;
    g_mtl[(size_t)l * DN * DN + i] = __float2bfloat16(v - __bfloat162float(h));
}

__global__ void uvc_kernel(const float* __restrict__ Wq, const float* __restrict__ Wk,
                           const float* __restrict__ bq, const float* __restrict__ bk) {
    int l = blockIdx.x;
    int wid = threadIdx.x >> 5, lane = threadIdx.x & 31;
    int k = blockIdx.y * 8 + wid;
    float su = 0.f, sv = 0.f;
    const float* wq = Wq + (size_t)l * DN * DN + (size_t)k * DN;
    const float* wk = Wk + (size_t)l * DN * DN + (size_t)k * DN;
    for (int d = lane; d < DN; d += 32) {
        su += wq[d] * bk[l * DN + d];
        sv += wk[d] * bq[l * DN + d];
    }
#pragma unroll
    for (int o = 16; o; o >>= 1) {
        su += __shfl_xor_sync(0xffffffffu, su, o);
        sv += __shfl_xor_sync(0xffffffffu, sv, o);
    }
    if (lane == 0) {
        g_u[l * DN + k] = su;
        g_v[l * DN + k] = sv;
    }
    if (blockIdx.y == 0 && wid == 0) {
        float c = 0.f;
        for (int d = lane; d < DN; d += 32) c += bq[l * DN + d] * bk[l * DN + d];
#pragma unroll
        for (int o = 16; o; o >>= 1) c += __shfl_xor_sync(0xffffffffu, c, o);
        if (lane == 0) g_cc[l] = c;
    }
}

// ---------------- conv weight transpose ----------------
__global__ void wtrans_kernel(const float* __restrict__ w, int C) {
    int i = blockIdx.x * blockDim.x + threadIdx.x;
    int tot = DN * C * 3;
    if (i < tot) {
        int d = i / (C * 3);
        int r = i - d * (C * 3);
        g_wT[r * DN + d] = w[i];
    }
}

// ---------------- circular conv + PE -> Z (bf16 hi/lo) ----------------
template <int T, int C>
__global__ __launch_bounds__(256) void conv_embed_kernel() {
    constexpr int CHUNK = 8;
    __shared__ float sx[LN];
    __shared__ float sw[3 * CHUNK * DN];
    int bm = blockIdx.x;
    int d = threadIdx.x;
    for (int i = threadIdx.x; i < LN; i += blockDim.x) sx[i] = g_xt[(size_t)bm * LN + i];
    float acc[T];
#pragma unroll
    for (int t = 0; t < T; t++) acc[t] = 0.f;
    for (int c0 = 0; c0 < C; c0 += CHUNK) {
        int cw = (C - c0 < CHUNK) ? (C - c0) : CHUNK;
        __syncthreads();
        for (int i = threadIdx.x; i < cw * 3 * DN; i += blockDim.x)
            sw[i] = g_wT[c0 * 3 * DN + i];
        __syncthreads();
        for (int ci = 0; ci < cw; ci++) {
            int c = c0 + ci;
            float w0 = sw[(ci * 3 + 0) * DN + d];
            float w1 = sw[(ci * 3 + 1) * DN + d];
            float w2 = sw[(ci * 3 + 2) * DN + d];
#pragma unroll
            for (int t = 0; t < T; t++) {
                int tm = (t == 0) ? (T - 1) : (t - 1);
                int tp = (t == T - 1) ? 0 : (t + 1);
                acc[t] += w0 * sx[tm * C + c] + w1 * sx[t * C + c] + w2 * sx[tp * C + c];
            }
        }
    }
    float freq = expf(-(float)(2 * (d >> 1)) * (9.210340371976184f / 256.f));
    bool isodd = (d & 1);
#pragma unroll
    for (int t = 0; t < T; t++) {
        float arg = (float)t * freq;
        float pe = isodd ? cosf(arg) : sinf(arg);
        float zv = acc[t] + pe;
        size_t ridx = ((size_t)bm * T + t) * DN + d;
        __nv_bfloat16 h = __float2bfloat16(zv);
        g_zh[ridx] = h;
        g_zl[ridx] = __float2bfloat16(zv - __bfloat162float(h));
    }
}

// ---------------- fused: for all 3 layers, G = Z@Meff, S = softmax(...) ----------------
static constexpr int OZH = 0;         // Zh [128][256] bf16 swizzled (65536)
static constexpr int OZL = 65536;     // Zl
static constexpr int OGH = 131072;    // Gh half [128][128] bf16 (32768)
static constexpr int OGL = 163840;    // Gl half
static constexpr int OBH = 196608;    // Bh chunk [128 n][64 k] (16384)
static constexpr int OBL = 212992;    // Bl chunk
static constexpr int OSS = 196608;    // S overlay (reuses B region, <= 32KB)
static constexpr int OU  = 229376;    // u (1024)
static constexpr int OV  = 230400;    // v (1024)
static constexpr int OZU = 231424;    // zu (512)
static constexpr int OZV = 231936;    // zv (512)
static constexpr int FUSED_SMEM = 232448;

template <int T>
__global__ __launch_bounds__(512, 1) void fused_kernel() {
    constexpr int MT = (T + 15) / 16;
    constexpr int QB = (T < 16) ? (16 / T) : 1;
    constexpr int NB = (T < 16) ? (8 * QB) : (128 / T);
    constexpr int NTILES = (T < 16) ? 8 : (NB * MT * MT);
    constexpr int TC = (T + 3) & ~3;
    constexpr int SLOTS = (NTILES + 15) / 16;

    extern __shared__ __align__(128) char smem[];
    const uint32_t sb = smem_u32(smem);
    const int tid = threadIdx.x;
    const int lane = tid & 31;
    const int wid = tid >> 5;
    const int bm0 = blockIdx.x * NB;
    const int nbm = min(NB, BM - bm0);
    const int nrows = nbm * T;

    // ---- load Z rows once, zero pad rows ----
    const __nv_bfloat16* Zh = g_zh + (size_t)bm0 * T * DN;
    const __nv_bfloat16* Zl = g_zl + (size_t)bm0 * T * DN;
    for (int idx = tid; idx < nrows * 32; idx += 512) {
        int r = idx >> 5, c = idx & 31;
        uint32_t off = r * 512 + ((c ^ (r & 7)) << 4);
        cp_async16(sb + OZH + off, Zh + (size_t)r * DN + c * 8);
        cp_async16(sb + OZL + off, Zl + (size_t)r * DN + c * 8);
    }
    asm volatile("cp.async.commit_group;" ::: "memory");
    for (int idx = tid + nrows * 32; idx < 128 * 32; idx += 512) {
        int r = idx >> 5, c = idx & 31;
        uint32_t off = r * 512 + (c << 4);
        *(uint4*)(smem + OZH + off) = make_uint4(0, 0, 0, 0);
        *(uint4*)(smem + OZL + off) = make_uint4(0, 0, 0, 0);
    }
    asm volatile("cp.async.wait_group 0;" ::: "memory");
    __syncthreads();

    const int wm = wid >> 2, wn = wid & 3;
    const int rA = lane & 15;
    const int chsel = lane >> 4;
    const int br0 = tid >> 3, bc0 = tid & 7;
    const int br1 = (tid + 512) >> 3, bc1 = (tid + 512) & 7;
    const uint32_t bo0 = br0 * 128 + ((bc0 ^ (br0 & 7)) << 4);
    const uint32_t bo1 = br1 * 128 + ((bc1 ^ (br1 & 7)) << 4);

    for (int layer = 0; layer < ELN; layer++) {
        __syncthreads();  // prior layer's softmax done reading sS/zu/zv

        // stage u/v
        if (tid < DN) ((float*)(smem + OU))[tid] = g_u[layer * DN + tid];
        else if (tid < 2 * DN) ((float*)(smem + OV))[tid - DN] = g_v[layer * DN + tid - DN];
        __syncthreads();

        // zu/zv per row (4 threads per row)
        {
            int r = tid >> 2, p = tid & 3;
            float au = 0.f, av = 0.f;
            if (r < nrows) {
                const float* su = (const float*)(smem + OU);
                const float* sv = (const float*)(smem + OV);
                for (int c = p * 8; c < p * 8 + 8; c++) {
                    uint32_t off = r * 512 + ((c ^ (r & 7)) << 4);
                    const __nv_bfloat16* ph = (const __nv_bfloat16*)(smem + OZH + off);
                    const __nv_bfloat16* pl = (const __nv_bfloat16*)(smem + OZL + off);
#pragma unroll
                    for (int j = 0; j < 8; j++) {
                        float z = __bfloat162float(ph[j]) + __bfloat162float(pl[j]);
                        au += z * su[c * 8 + j];
                        av += z * sv[c * 8 + j];
                    }
                }
            }
            au += __shfl_xor_sync(0xffffffffu, au, 1);
            au += __shfl_xor_sync(0xffffffffu, au, 2);
            av += __shfl_xor_sync(0xffffffffu, av, 1);
            av += __shfl_xor_sync(0xffffffffu, av, 2);
            if (p == 0 && r < nrows) {
                ((float*)(smem + OZU))[r] = au;
                ((float*)(smem + OZV))[r] = av;
            }
        }

        float sfr[SLOTS][2][4];
#pragma unroll
        for (int s = 0; s < SLOTS; s++)
#pragma unroll
            for (int j = 0; j < 2; j++)
#pragma unroll
                for (int q = 0; q < 4; q++) sfr[s][j][q] = 0.f;

        const __nv_bfloat16* Bh_src = g_mth + (size_t)layer * DN * DN;
        const __nv_bfloat16* Bl_src = g_mtl + (size_t)layer * DN * DN;

        for (int h = 0; h < 2; h++) {
            float acc[2][4][4];
#pragma unroll
            for (int mt = 0; mt < 2; mt++)
#pragma unroll
                for (int j = 0; j < 4; j++)
#pragma unroll
                    for (int q = 0; q < 4; q++) acc[mt][j][q] = 0.f;

            uint4 pre0, pre1, pre2, pre3;
            {
                const __nv_bfloat16* bh = Bh_src + (size_t)(h * 128) * DN;
                const __nv_bfloat16* bl = Bl_src + (size_t)(h * 128) * DN;
                pre0 = *(const uint4*)(bh + (size_t)br0 * DN + bc0 * 8);
                pre1 = *(const uint4*)(bh + (size_t)br1 * DN + bc1 * 8);
                pre2 = *(const uint4*)(bl + (size_t)br0 * DN + bc0 * 8);
                pre3 = *(const uint4*)(bl + (size_t)br1 * DN + bc1 * 8);
            }
            for (int kc = 0; kc < 4; kc++) {
                __syncthreads();
                *(uint4*)(smem + OBH + bo0) = pre0;
                *(uint4*)(smem + OBH + bo1) = pre1;
                *(uint4*)(smem + OBL + bo0) = pre2;
                *(uint4*)(smem + OBL + bo1) = pre3;
                __syncthreads();
                if (kc < 3) {
                    const __nv_bfloat16* bh = Bh_src + (size_t)(h * 128) * DN + (kc + 1) * 64;
                    const __nv_bfloat16* bl = Bl_src + (size_t)(h * 128) * DN + (kc + 1) * 64;
                    pre0 = *(const uint4*)(bh + (size_t)br0 * DN + bc0 * 8);
                    pre1 = *(const uint4*)(bh + (size_t)br1 * DN + bc1 * 8);
                    pre2 = *(const uint4*)(bl + (size_t)br0 * DN + bc0 * 8);
                    pre3 = *(const uint4*)(bl + (size_t)br1 * DN + bc1 * 8);
                }
#pragma unroll
                for (int ks = 0; ks < 4; ks++) {
                    int chA = kc * 8 + ks * 2 + chsel;
                    uint32_t ah[2][4], al[2][4];
#pragma unroll
                    for (int mt = 0; mt < 2; mt++) {
                        int row = wm * 32 + mt * 16 + rA;
                        uint32_t ad = sb + OZH + row * 512 + ((chA ^ (row & 7)) << 4);
                        LDMX4(ah[mt][0], ah[mt][1], ah[mt][2], ah[mt][3], ad);
                        LDMX4(al[mt][0], al[mt][1], al[mt][2], al[mt][3], ad + 65536);
                    }
                    uint32_t bh[2][4], bl[2][4];
#pragma unroll
                    for (int ng = 0; ng < 2; ng++) {
                        int row = wn * 32 + ng * 16 + rA;
                        uint32_t bd = sb + OBH + row * 128 + (((ks * 2 + chsel) ^ (row & 7)) << 4);
                        LDMX4(bh[ng][0], bh[ng][1], bh[ng][2], bh[ng][3], bd);
                        LDMX4(bl[ng][0], bl[ng][1], bl[ng][2], bl[ng][3], bd + 16384);
                    }
#pragma unroll
                    for (int mt = 0; mt < 2; mt++)
#pragma unroll
                        for (int ng = 0; ng < 2; ng++) {
                            mma16816(acc[mt][ng * 2 + 0], ah[mt], bh[ng][0], bh[ng][2]);
                            mma16816(acc[mt][ng * 2 + 1], ah[mt], bh[ng][1], bh[ng][3]);
                            mma16816(acc[mt][ng * 2 + 0], ah[mt], bl[ng][0], bl[ng][2]);
                            mma16816(acc[mt][ng * 2 + 1], ah[mt], bl[ng][1], bl[ng][3]);
                            mma16816(acc[mt][ng * 2 + 0], al[mt], bh[ng][0], bh[ng][2]);
                            mma16816(acc[mt][ng * 2 + 1], al[mt], bh[ng][1], bh[ng][3]);
                        }
                }
            }
            __syncthreads();
            // G accum -> bf16 hi/lo smem
#pragma unroll
            for (int mt = 0; mt < 2; mt++)
#pragma unroll
                for (int j = 0; j < 4; j++) {
                    int c = wn * 32 + (j >> 1) * 16 + (j & 1) * 8 + (lane & 3) * 2;
#pragma unroll
                    for (int half = 0; half < 2; half++) {
                        int r = wm * 32 + mt * 16 + (lane >> 2) + half * 8;
                        float v0 = acc[mt][j][half * 2 + 0];
                        float v1 = acc[mt][j][half * 2 + 1];
                        uint32_t off = r * 256 + ((((c >> 3)) ^ (r & 7)) << 4) + (c & 7) * 2;
                        __nv_bfloat16 h0 = __float2bfloat16(v0);
                        __nv_bfloat16 h1 = __float2bfloat16(v1);
                        *(__nv_bfloat162*)(smem + OGH + off) = __nv_bfloat162(h0, h1);
                        __nv_bfloat16 l0 = __float2bfloat16(v0 - __bfloat162float(h0));
                        __nv_bfloat16 l1 = __float2bfloat16(v1 - __bfloat162float(h1));
                        *(__nv_bfloat162*)(smem + OGL + off) = __nv_bfloat162(l0, l1);
                    }
                }
            __syncthreads();
            // phase2: S += G_half @ Z_half^T on diagonal tiles
            int slot = 0;
            for (int t = wid; t < NTILES; t += 16, slot++) {
                int rb, cb;
                if (T < 16) {
                    rb = cb = t * QB * T;
                } else {
                    int tbm = t / (MT * MT);
                    int rem = t % (MT * MT);
                    rb = tbm * T + (rem / MT) * 16;
                    cb = tbm * T + (rem % MT) * 16;
                }
#pragma unroll
                for (int kc = 0; kc < 8; kc++) {
                    int ch = kc * 2 + chsel;
                    int arow = rb + rA;
                    uint32_t aad = sb + OGH + arow * 256 + ((ch ^ (arow & 7)) << 4);
                    uint32_t gh[4], gl[4];
                    LDMX4(gh[0], gh[1], gh[2], gh[3], aad);
                    LDMX4(gl[0], gl[1], gl[2], gl[3], aad + 32768);
                    int brow = cb + rA;
                    int chz = h * 16 + ch;
                    uint32_t bad = sb + OZH + brow * 512 + ((chz ^ (brow & 7)) << 4);
                    uint32_t zh2[4], zl2[4];
                    LDMX4(zh2[0], zh2[1], zh2[2], zh2[3], bad);
                    LDMX4(zl2[0], zl2[1], zl2[2], zl2[3], bad + 65536);
                    mma16816(sfr[slot][0], gh, zh2[0], zh2[2]);
                    mma16816(sfr[slot][1], gh, zh2[1], zh2[3]);
                    mma16816(sfr[slot][0], gh, zl2[0], zl2[2]);
                    mma16816(sfr[slot][1], gh, zl2[1], zl2[3]);
                    mma16816(sfr[slot][0], gl, zh2[0], zh2[2]);
                    mma16816(sfr[slot][1], gl, zh2[1], zh2[3]);
                }
            }
        }
        __syncthreads();

        // ---- S frags -> smem overlay ----
        float* sS = (float*)(smem + OSS);
        {
            int slot = 0;
            for (int t = wid; t < NTILES; t += 16, slot++) {
                int tbm = -1, ti = 0, tj = 0;
                if (T >= 16) {
                    tbm = t / (MT * MT);
                    int rem = t % (MT * MT);
                    ti = rem / MT;
                    tj = rem % MT;
                }
                int fr = lane >> 2, fc = (lane & 3) * 2;
#pragma unroll
                for (int j = 0; j < 2; j++)
#pragma unroll
                    for (int q = 0; q < 4; q++) {
                        int rr = fr + (q >> 1) * 8;
                        int cc = fc + (q & 1) + j * 8;
                        float v = sfr[slot][j][q];
                        if (T < 16) {
                            int qr = rr / T, qc = cc / T;
                            if (qr == qc && qr < QB) {
                                int bm = t * QB + qr;
                                if (bm < nbm) sS[(bm * T + rr - qr * T) * TC + (cc - qc * T)] = v;
                            }
                        } else {
                            if (tbm < nbm && ti * 16 + rr < T && tj * 16 + cc < T)
                                sS[(tbm * T + ti * 16 + rr) * TC + tj * 16 + cc] = v;
                        }
                    }
            }
        }
        __syncthreads();

        // ---- softmax rows -> g_S ----
        float cterm = g_cc[layer];
        const float* zu = (const float*)(smem + OZU);
        const float* zv = (const float*)(smem + OZV);
        int e = lane;
        for (int rho = wid; rho < nrows; rho += 16) {
            int bm = rho / T, l = rho % T;
            const float* row = sS + (bm * T + l) * TC;
            bool v0 = (e < T);
            bool v1 = (T > 32) && (e + 32 < T);
            float zul = zu[rho];
            float x0 = v0 ? SCALE * (row[e] + zul + zv[bm * T + e] + cterm) : -1e30f;
            float x1 = v1 ? SCALE * (row[e + 32] + zul + zv[bm * T + e + 32] + cterm) : -1e30f;
            float mx = fmaxf(x0, x1);
#pragma unroll
            for (int o = 16; o; o >>= 1) mx = fmaxf(mx, __shfl_xor_sync(0xffffffffu, mx, o));
            float e0 = v0 ? __expf(x0 - mx) : 0.f;
            float e1 = v1 ? __expf(x1 - mx) : 0.f;
            float ssum = e0 + e1;
#pragma unroll
            for (int o = 16; o; o >>= 1) ssum += __shfl_xor_sync(0xffffffffu, ssum, o);
            float inv = 1.0f / ssum;
            float* So = g_S + ((size_t)layer * BM + bm0 + bm) * T * T + (size_t)l * T;
            if (v0) So[e] = e0 * inv;
            if (v1) So[e + 32] = e1 * inv;
        }
    }
}

// ---------------- channel mean + expand (fused) ----------------
template <int T, int P, bool TILE>
__global__ __launch_bounds__(256) void mean_expand_kernel(float* __restrict__ out) {
    constexpr int TT = T * T;
    __shared__ float sA[TT];
    int b = blockIdx.x, layer = blockIdx.y;
    const float* Sb = g_S + ((size_t)layer * BM + (size_t)b * MN) * TT;
    for (int r = threadIdx.x; r < TT; r += 256) {
        float s = 0.f;
#pragma unroll 5
        for (int m = 0; m < MN; m++) s += Sb[(size_t)m * TT + r];
        sA[r] = s * (1.0f / MN);
    }
    __syncthreads();
    float* ob = out + ((size_t)layer * BN + b) * LL;
    for (int i = threadIdx.x; i < LL; i += 256) {
        int l = i / LN, s = i - l * LN;
        int al = TILE ? (l % P) : (l / P);
        int as = TILE ? (s % P) : (s / P);
        ob[i] = sA[al * T + as];
    }
}

// ---------------- host orchestration ----------------
template <int T, int C, int P, bool TILE>
static void run_branch(const float* w, float* outbase) {
    wtrans_kernel<<<(DN * C * 3 + 255) / 256, 256>>>(w, C);
    conv_embed_kernel<T, C><<<BM, 256>>>();
    constexpr int QB = (T < 16) ? (16 / T) : 1;
    constexpr int NB = (T < 16) ? (8 * QB) : (128 / T);
    int nblk = (BM + NB - 1) / NB;
    cudaFuncSetAttribute(fused_kernel<T>, cudaFuncAttributeMaxDynamicSharedMemorySize, FUSED_SMEM);
    fused_kernel<T><<<nblk, 512, FUSED_SMEM>>>();
    mean_expand_kernel<T, P, TILE><<<dim3(BN, ELN), 256>>>(outbase);
}

extern "C" void kernel_launch(void* const* d_in, const int* in_sizes, int n_in,
                              void* d_out, int out_size) {
    const float* x = (const float*)d_in[0];
    const float* Wq = (const float*)d_in[7];
    const float* bq = (const float*)d_in[8];
    const float* Wk = (const float*)d_in[9];
    const float* bk = (const float*)d_in[10];
    float* out = (float*)d_out;

    revin_kernel<<<BN, 256>>>(x);
    meff_kernel<<<dim3(16, 16, ELN), dim3(16, 16)>>>(Wq, Wk);
    meffT_kernel<<<dim3(256, ELN), 256>>>();
    uvc_kernel<<<dim3(ELN, 32), 256>>>(Wq, Wk, bq, bk);

    run_branch<35, 3, 3, false>((const float*)d_in[1], out + (size_t)0 * BN * LL);
    run_branch<3, 35, 3, true>((const float*)d_in[2], out + (size_t)9 * BN * LL);

    run_branch<21, 5, 5, false>((const float*)d_in[3], out + (size_t)3 * BN * LL);
    run_branch<5, 21, 5, true>((const float*)d_in[4], out + (size_t)12 * BN * LL);

    run_branch<15, 7, 7, false>((const float*)d_in[5], out + (size_t)6 * BN * LL);
    run_branch<7, 15, 7, true>((const float*)d_in[6], out + (size_t)15 * BN * LL);
}

// round 8
// speedup vs baseline: 3.7802x; 1.2987x over previous
#include <cuda_runtime.h>
#include <cuda_fp16.h>
#include <math.h>
#include <cstdint>

#define BN 128
#define LN 105
#define MN 55
#define DN 256
#define ELN 3
static constexpr int BM = BN * MN;      // 7040
static constexpr int LL = LN * LN;      // 11025
static constexpr float SCALE = 0.0625f; // 1/sqrt(256)

// ---------------- scratch (device globals) ----------------
__device__ __align__(128) float g_xt[BM * LN];
__device__ __align__(128) __half g_zh[(size_t)BM * 35 * DN];       // fp16 Z
__device__ __align__(128) float g_wT[66048];                        // all branches
__device__ __align__(128) float g_meff[ELN * DN * DN];
__device__ __align__(128) __half g_mth[ELN * DN * DN];              // MeffT hi [n][k]
__device__ __align__(128) __half g_mtl[ELN * DN * DN];              // MeffT lo
__device__ float g_u[ELN * DN];
__device__ float g_v[ELN * DN];
__device__ float g_cc[ELN];
__device__ __align__(128) float g_S[(size_t)ELN * BM * 35 * 35];

// ---------------- helpers ----------------
__device__ __forceinline__ uint32_t smem_u32(const void* p) {
    uint32_t a;
    asm("{ .reg .u64 t; cvta.to.shared.u64 t, %1; cvt.u32.u64 %0, t; }" : "=r"(a) : "l"(p));
    return a;
}
__device__ __forceinline__ void cp_async16(uint32_t saddr, const void* gptr) {
    asm volatile("cp.async.ca.shared.global [%0], [%1], 16;" :: "r"(saddr), "l"(gptr) : "memory");
}
__device__ __forceinline__ void mma16816(float* d, const uint32_t* a, uint32_t b0, uint32_t b1) {
    asm volatile(
        "mma.sync.aligned.m16n8k16.row.col.f32.f16.f16.f32 "
        "{%0,%1,%2,%3}, {%4,%5,%6,%7}, {%8,%9}, {%0,%1,%2,%3};"
        : "+f"(d[0]), "+f"(d[1]), "+f"(d[2]), "+f"(d[3])
        : "r"(a[0]), "r"(a[1]), "r"(a[2]), "r"(a[3]), "r"(b0), "r"(b1));
}
#define LDMX4(r0, r1, r2, r3, addr) \
    asm volatile("ldmatrix.sync.aligned.m8n8.x4.shared.b16 {%0,%1,%2,%3}, [%4];" \
        : "=r"(r0), "=r"(r1), "=r"(r2), "=r"(r3) : "r"(addr))

// ---------------- K1: revin + meff + uvc + wtrans(all branches) ----------------
__constant__ int c_wcum[7] = {0, 2304, 29184, 33024, 49152, 54528, 66048};
__constant__ int c_wC[6] = {3, 35, 5, 21, 7, 15};

__global__ __launch_bounds__(256) void k1_kernel(
    const float* __restrict__ x,
    const float* __restrict__ Wq, const float* __restrict__ Wk,
    const float* __restrict__ bq, const float* __restrict__ bk,
    const float* __restrict__ w0, const float* __restrict__ w1,
    const float* __restrict__ w2, const float* __restrict__ w3,
    const float* __restrict__ w4, const float* __restrict__ w5) {
    int blk = blockIdx.x;
    int tid = threadIdx.x;
    if (blk < 128) {
        // ---- revin ----
        __shared__ float sx[LN * MN];
        __shared__ float smean[MN], sinv[MN];
        int b = blk;
        const float* xb = x + (size_t)b * LN * MN;
        for (int i = tid; i < LN * MN; i += 256) sx[i] = xb[i];
        __syncthreads();
        for (int m = tid; m < MN; m += 256) {
            float s = 0.f, s2 = 0.f;
            for (int l = 0; l < LN; l++) { float v = sx[l * MN + m]; s += v; s2 += v * v; }
            float mean = s * (1.0f / LN);
            float var = s2 * (1.0f / LN) - mean * mean;
            smean[m] = mean;
            sinv[m] = rsqrtf(var + 1e-5f);
        }
        __syncthreads();
        float* ob = g_xt + (size_t)b * MN * LN;
        for (int i = tid; i < MN * LN; i += 256) {
            int m = i / LN, l = i - m * LN;
            ob[i] = (sx[l * MN + m] - smean[m]) * sinv[m];
        }
    } else if (blk < 896) {
        // ---- meff: Wq @ Wk^T ----
        __shared__ float sq[16][17], sk[16][17];
        int u = blk - 128;
        int l = u >> 8;
        int rem = u & 255;
        int i0 = (rem >> 4) * 16, j0 = (rem & 15) * 16;
        int ty = tid >> 4, tx = tid & 15;
        float acc = 0.f;
        const float* wq = Wq + (size_t)l * DN * DN;
        const float* wk = Wk + (size_t)l * DN * DN;
        for (int k0 = 0; k0 < DN; k0 += 16) {
            sq[ty][tx] = wq[(i0 + ty) * DN + k0 + tx];
            sk[ty][tx] = wk[(j0 + ty) * DN + k0 + tx];
            __syncthreads();
#pragma unroll
            for (int kk = 0; kk < 16; kk++) acc += sq[ty][kk] * sk[tx][kk];
            __syncthreads();
        }
        g_meff[(size_t)l * DN * DN + (i0 + ty) * DN + j0 + tx] = acc;
    } else if (blk < 992) {
        // ---- uvc ----
        int u = blk - 896;
        int l = u >> 5, r = u & 31;
        int wid = tid >> 5, lane = tid & 31;
        int k = r * 8 + wid;
        float su = 0.f, sv = 0.f;
        const float* wq = Wq + (size_t)l * DN * DN + (size_t)k * DN;
        const float* wk = Wk + (size_t)l * DN * DN + (size_t)k * DN;
        for (int d = lane; d < DN; d += 32) {
            su += wq[d] * bk[l * DN + d];
            sv += wk[d] * bq[l * DN + d];
        }
#pragma unroll
        for (int o = 16; o; o >>= 1) {
            su += __shfl_xor_sync(0xffffffffu, su, o);
            sv += __shfl_xor_sync(0xffffffffu, sv, o);
        }
        if (lane == 0) {
            g_u[l * DN + k] = su;
            g_v[l * DN + k] = sv;
        }
        if (r == 0 && wid == 0) {
            float c = 0.f;
            for (int d = lane; d < DN; d += 32) c += bq[l * DN + d] * bk[l * DN + d];
#pragma unroll
            for (int o = 16; o; o >>= 1) c += __shfl_xor_sync(0xffffffffu, c, o);
            if (lane == 0) g_cc[l] = c;
        }
    } else {
        // ---- wtrans (all 6 branches) ----
        int i = (blk - 992) * 256 + tid;
        if (i < 66048) {
            int br = 0;
#pragma unroll
            for (int q = 1; q < 6; q++)
                if (i >= c_wcum[q]) br = q;
            const float* wp = br == 0 ? w0 : br == 1 ? w1 : br == 2 ? w2 : br == 3 ? w3 : br == 4 ? w4 : w5;
            int j = i - c_wcum[br];
            int C3 = c_wC[br] * 3;
            int d = j / C3, r = j - d * C3;
            g_wT[c_wcum[br] + r * DN + d] = wp[j];
        }
    }
}

// ---------------- meffT: fp16 hi/lo split of Meff^T ----------------
__global__ void meffT_kernel() {
    int l = blockIdx.y;
    int i = blockIdx.x * 256 + threadIdx.x;   // n*256+k
    int n = i >> 8, k = i & 255;
    float v = g_meff[(size_t)l * DN * DN + k * DN + n];
    __half h = __float2half_rn(v);
    g_mth[(size_t)l * DN * DN + i] = h;
    g_mtl[(size_t)l * DN * DN + i] = __float2half_rn(v - __half2float(h));
}

// ---------------- circular conv + PE -> Z (fp16) ----------------
template <int T, int C>
__global__ __launch_bounds__(256) void conv_embed_kernel(int woff) {
    constexpr int CHUNK = 8;
    __shared__ float sx[LN];
    __shared__ float sw[3 * CHUNK * DN];
    int bm = blockIdx.x;
    int d = threadIdx.x;
    for (int i = threadIdx.x; i < LN; i += blockDim.x) sx[i] = g_xt[(size_t)bm * LN + i];
    float acc[T];
#pragma unroll
    for (int t = 0; t < T; t++) acc[t] = 0.f;
    const float* wT = g_wT + woff;
    for (int c0 = 0; c0 < C; c0 += CHUNK) {
        int cw = (C - c0 < CHUNK) ? (C - c0) : CHUNK;
        __syncthreads();
        for (int i = threadIdx.x; i < cw * 3 * DN; i += blockDim.x)
            sw[i] = wT[c0 * 3 * DN + i];
        __syncthreads();
        for (int ci = 0; ci < cw; ci++) {
            int c = c0 + ci;
            float w0 = sw[(ci * 3 + 0) * DN + d];
            float w1 = sw[(ci * 3 + 1) * DN + d];
            float w2 = sw[(ci * 3 + 2) * DN + d];
#pragma unroll
            for (int t = 0; t < T; t++) {
                int tm = (t == 0) ? (T - 1) : (t - 1);
                int tp = (t == T - 1) ? 0 : (t + 1);
                acc[t] += w0 * sx[tm * C + c] + w1 * sx[t * C + c] + w2 * sx[tp * C + c];
            }
        }
    }
    float freq = expf(-(float)(2 * (d >> 1)) * (9.210340371976184f / 256.f));
    bool isodd = (d & 1);
#pragma unroll
    for (int t = 0; t < T; t++) {
        float arg = (float)t * freq;
        float pe = isodd ? cosf(arg) : sinf(arg);
        g_zh[((size_t)bm * T + t) * DN + d] = __float2half_rn(acc[t] + pe);
    }
}

// ---------------- fused: all 3 layers, G = Zh@(Mh+Ml), S = softmax((Gh+Gl)Zh^T+bias) --
static constexpr int OZH = 0;         // Zh [128][256] fp16 (65536)
static constexpr int OGH = 65536;     // Gh half [128][128] fp16 (32768)
static constexpr int OGL = 98304;     // Gl half
static constexpr int OBH = 131072;    // Bh chunk [128 n][64 k] fp16 (16384)
static constexpr int OBL = 147456;    // Bl chunk (16384)
static constexpr int OSS = 131072;    // S overlay (reuses B region, <= 32KB)
static constexpr int OU  = 163840;    // u [3][256] f32 (3072)
static constexpr int OV  = 166912;    // v (3072)
static constexpr int OZU = 169984;    // zu [3][128] (1536)
static constexpr int OZV = 171520;    // zv (1536)
static constexpr int FUSED_SMEM = 173056;

template <int T>
__global__ __launch_bounds__(512, 1) void fused_kernel() {
    constexpr int MT = (T + 15) / 16;
    constexpr int QB = (T < 16) ? (16 / T) : 1;
    constexpr int NB = (T < 16) ? (8 * QB) : (128 / T);
    constexpr int NTILES = (T < 16) ? 8 : (NB * MT * MT);
    constexpr int TC = (T + 3) & ~3;
    constexpr int SLOTS = (NTILES + 15) / 16;

    extern __shared__ __align__(128) char smem[];
    const uint32_t sb = smem_u32(smem);
    const int tid = threadIdx.x;
    const int lane = tid & 31;
    const int wid = tid >> 5;
    const int bm0 = blockIdx.x * NB;
    const int nbm = min(NB, BM - bm0);
    const int nrows = nbm * T;

    // ---- load Z rows once (fp16), zero pad rows, stage u/v for all layers ----
    const __half* Zh = g_zh + (size_t)bm0 * T * DN;
    for (int idx = tid; idx < nrows * 32; idx += 512) {
        int r = idx >> 5, c = idx & 31;
        uint32_t off = r * 512 + ((c ^ (r & 7)) << 4);
        cp_async16(sb + OZH + off, Zh + (size_t)r * DN + c * 8);
    }
    asm volatile("cp.async.commit_group;" ::: "memory");
    for (int idx = tid + nrows * 32; idx < 128 * 32; idx += 512) {
        int r = idx >> 5, c = idx & 31;
        *(uint4*)(smem + OZH + r * 512 + (c << 4)) = make_uint4(0, 0, 0, 0);
    }
    for (int i = tid; i < 768; i += 512) {     // FIXED: full 768-entry staging
        ((float*)(smem + OU))[i] = g_u[i];
        ((float*)(smem + OV))[i] = g_v[i];
    }
    asm volatile("cp.async.wait_group 0;" ::: "memory");
    __syncthreads();

    // ---- zu/zv per row for ALL 3 layers (4 threads per row) ----
    {
        int r = tid >> 2, p = tid & 3;
        float au[3] = {0.f, 0.f, 0.f}, av[3] = {0.f, 0.f, 0.f};
        if (r < nrows) {
            const float* su = (const float*)(smem + OU);
            const float* sv = (const float*)(smem + OV);
            for (int c = p * 8; c < p * 8 + 8; c++) {
                uint32_t off = r * 512 + ((c ^ (r & 7)) << 4);
                const __half* ph = (const __half*)(smem + OZH + off);
#pragma unroll
                for (int j = 0; j < 8; j++) {
                    float z = __half2float(ph[j]);
#pragma unroll
                    for (int l = 0; l < 3; l++) {
                        au[l] += z * su[l * DN + c * 8 + j];
                        av[l] += z * sv[l * DN + c * 8 + j];
                    }
                }
            }
        }
#pragma unroll
        for (int l = 0; l < 3; l++) {
            au[l] += __shfl_xor_sync(0xffffffffu, au[l], 1);
            au[l] += __shfl_xor_sync(0xffffffffu, au[l], 2);
            av[l] += __shfl_xor_sync(0xffffffffu, av[l], 1);
            av[l] += __shfl_xor_sync(0xffffffffu, av[l], 2);
        }
        if (p == 0 && r < nrows) {
#pragma unroll
            for (int l = 0; l < 3; l++) {
                ((float*)(smem + OZU))[l * 128 + r] = au[l];
                ((float*)(smem + OZV))[l * 128 + r] = av[l];
            }
        }
    }

    const int wm = wid >> 2, wn = wid & 3;
    const int rA = lane & 15;
    const int chsel = lane >> 4;
    const int br0 = tid >> 3, bc0 = tid & 7;
    const int br1 = (tid + 512) >> 3, bc1 = (tid + 512) & 7;
    const uint32_t bo0 = br0 * 128 + ((bc0 ^ (br0 & 7)) << 4);
    const uint32_t bo1 = br1 * 128 + ((bc1 ^ (br1 & 7)) << 4);

    for (int layer = 0; layer < ELN; layer++) {
        __syncthreads();  // prior layer's softmax done reading sS

        float sfr[SLOTS][2][4];
#pragma unroll
        for (int s = 0; s < SLOTS; s++)
#pragma unroll
            for (int j = 0; j < 2; j++)
#pragma unroll
                for (int q = 0; q < 4; q++) sfr[s][j][q] = 0.f;

        const __half* Bh_src = g_mth + (size_t)layer * DN * DN;
        const __half* Bl_src = g_mtl + (size_t)layer * DN * DN;

        for (int h = 0; h < 2; h++) {
            float acc[2][4][4];
#pragma unroll
            for (int mt = 0; mt < 2; mt++)
#pragma unroll
                for (int j = 0; j < 4; j++)
#pragma unroll
                    for (int q = 0; q < 4; q++) acc[mt][j][q] = 0.f;

            uint4 pre0, pre1, pre2, pre3;
            {
                const __half* bh = Bh_src + (size_t)(h * 128) * DN;
                const __half* bl = Bl_src + (size_t)(h * 128) * DN;
                pre0 = *(const uint4*)(bh + (size_t)br0 * DN + bc0 * 8);
                pre1 = *(const uint4*)(bh + (size_t)br1 * DN + bc1 * 8);
                pre2 = *(const uint4*)(bl + (size_t)br0 * DN + bc0 * 8);
                pre3 = *(const uint4*)(bl + (size_t)br1 * DN + bc1 * 8);
            }
            for (int kc = 0; kc < 4; kc++) {
                __syncthreads();
                *(uint4*)(smem + OBH + bo0) = pre0;
                *(uint4*)(smem + OBH + bo1) = pre1;
                *(uint4*)(smem + OBL + bo0) = pre2;
                *(uint4*)(smem + OBL + bo1) = pre3;
                __syncthreads();
                if (kc < 3) {
                    const __half* bh = Bh_src + (size_t)(h * 128) * DN + (kc + 1) * 64;
                    const __half* bl = Bl_src + (size_t)(h * 128) * DN + (kc + 1) * 64;
                    pre0 = *(const uint4*)(bh + (size_t)br0 * DN + bc0 * 8);
                    pre1 = *(const uint4*)(bh + (size_t)br1 * DN + bc1 * 8);
                    pre2 = *(const uint4*)(bl + (size_t)br0 * DN + bc0 * 8);
                    pre3 = *(const uint4*)(bl + (size_t)br1 * DN + bc1 * 8);
                }
#pragma unroll
                for (int ks = 0; ks < 4; ks++) {
                    int chA = kc * 8 + ks * 2 + chsel;
                    uint32_t ah[2][4];
#pragma unroll
                    for (int mt = 0; mt < 2; mt++) {
                        int row = wm * 32 + mt * 16 + rA;
                        uint32_t ad = sb + OZH + row * 512 + ((chA ^ (row & 7)) << 4);
                        LDMX4(ah[mt][0], ah[mt][1], ah[mt][2], ah[mt][3], ad);
                    }
                    uint32_t bh[2][4], bl[2][4];
#pragma unroll
                    for (int ng = 0; ng < 2; ng++) {
                        int row = wn * 32 + ng * 16 + rA;
                        uint32_t bd = sb + OBH + row * 128 + (((ks * 2 + chsel) ^ (row & 7)) << 4);
                        LDMX4(bh[ng][0], bh[ng][1], bh[ng][2], bh[ng][3], bd);
                        LDMX4(bl[ng][0], bl[ng][1], bl[ng][2], bl[ng][3], bd + 16384);
                    }
#pragma unroll
                    for (int mt = 0; mt < 2; mt++)
#pragma unroll
                        for (int ng = 0; ng < 2; ng++) {
                            mma16816(acc[mt][ng * 2 + 0], ah[mt], bh[ng][0], bh[ng][2]);
                            mma16816(acc[mt][ng * 2 + 1], ah[mt], bh[ng][1], bh[ng][3]);
                            mma16816(acc[mt][ng * 2 + 0], ah[mt], bl[ng][0], bl[ng][2]);
                            mma16816(acc[mt][ng * 2 + 1], ah[mt], bl[ng][1], bl[ng][3]);
                        }
                }
            }
            __syncthreads();
            // G accum -> fp16 hi/lo smem
#pragma unroll
            for (int mt = 0; mt < 2; mt++)
#pragma unroll
                for (int j = 0; j < 4; j++) {
                    int c = wn * 32 + (j >> 1) * 16 + (j & 1) * 8 + (lane & 3) * 2;
#pragma unroll
                    for (int half = 0; half < 2; half++) {
                        int r = wm * 32 + mt * 16 + (lane >> 2) + half * 8;
                        float v0 = acc[mt][j][half * 2 + 0];
                        float v1 = acc[mt][j][half * 2 + 1];
                        uint32_t off = r * 256 + ((((c >> 3)) ^ (r & 7)) << 4) + (c & 7) * 2;
                        __half h0 = __float2half_rn(v0);
                        __half h1 = __float2half_rn(v1);
                        *(__half2*)(smem + OGH + off) = __half2(h0, h1);
                        __half l0 = __float2half_rn(v0 - __half2float(h0));
                        __half l1 = __float2half_rn(v1 - __half2float(h1));
                        *(__half2*)(smem + OGL + off) = __half2(l0, l1);
                    }
                }
            __syncthreads();
            // phase2: S += (Gh+Gl) @ Zh_half^T on diagonal tiles
            int slot = 0;
            for (int t = wid; t < NTILES; t += 16, slot++) {
                int rb, cb;
                if (T < 16) {
                    rb = cb = t * QB * T;
                } else {
                    int tbm = t / (MT * MT);
                    int rem = t % (MT * MT);
                    rb = tbm * T + (rem / MT) * 16;
                    cb = tbm * T + (rem % MT) * 16;
                }
#pragma unroll
                for (int kc = 0; kc < 8; kc++) {
                    int ch = kc * 2 + chsel;
                    int arow = rb + rA;
                    uint32_t aad = sb + OGH + arow * 256 + ((ch ^ (arow & 7)) << 4);
                    uint32_t gh[4], gl[4];
                    LDMX4(gh[0], gh[1], gh[2], gh[3], aad);
                    LDMX4(gl[0], gl[1], gl[2], gl[3], aad + 32768);
                    int brow = cb + rA;
                    int chz = h * 16 + ch;
                    uint32_t bad = sb + OZH + brow * 512 + ((chz ^ (brow & 7)) << 4);
                    uint32_t zh2[4];
                    LDMX4(zh2[0], zh2[1], zh2[2], zh2[3], bad);
                    mma16816(sfr[slot][0], gh, zh2[0], zh2[2]);
                    mma16816(sfr[slot][1], gh, zh2[1], zh2[3]);
                    mma16816(sfr[slot][0], gl, zh2[0], zh2[2]);
                    mma16816(sfr[slot][1], gl, zh2[1], zh2[3]);
                }
            }
        }
        __syncthreads();

        // ---- S frags -> smem overlay ----
        float* sS = (float*)(smem + OSS);
        {
            int slot = 0;
            for (int t = wid; t < NTILES; t += 16, slot++) {
                int tbm = -1, ti = 0, tj = 0;
                if (T >= 16) {
                    tbm = t / (MT * MT);
                    int rem = t % (MT * MT);
                    ti = rem / MT;
                    tj = rem % MT;
                }
                int fr = lane >> 2, fc = (lane & 3) * 2;
#pragma unroll
                for (int j = 0; j < 2; j++)
#pragma unroll
                    for (int q = 0; q < 4; q++) {
                        int rr = fr + (q >> 1) * 8;
                        int cc = fc + (q & 1) + j * 8;
                        float v = sfr[slot][j][q];
                        if (T < 16) {
                            int qr = rr / T, qc = cc / T;
                            if (qr == qc && qr < QB) {
                                int bm = t * QB + qr;
                                if (bm < nbm) sS[(bm * T + rr - qr * T) * TC + (cc - qc * T)] = v;
                            }
                        } else {
                            if (tbm < nbm && ti * 16 + rr < T && tj * 16 + cc < T)
                                sS[(tbm * T + ti * 16 + rr) * TC + tj * 16 + cc] = v;
                        }
                    }
            }
        }
        __syncthreads();

        // ---- softmax rows -> g_S ----
        float cterm = g_cc[layer];
        const float* zu = (const float*)(smem + OZU) + layer * 128;
        const float* zv = (const float*)(smem + OZV) + layer * 128;
        int e = lane;
        for (int rho = wid; rho < nrows; rho += 16) {
            int bm = rho / T, l = rho % T;
            const float* row = sS + (bm * T + l) * TC;
            bool v0 = (e < T);
            bool v1 = (T > 32) && (e + 32 < T);
            float zul = zu[rho];
            float x0 = v0 ? SCALE * (row[e] + zul + zv[bm * T + e] + cterm) : -1e30f;
            float x1 = v1 ? SCALE * (row[e + 32] + zul + zv[bm * T + e + 32] + cterm) : -1e30f;
            float mx = fmaxf(x0, x1);
#pragma unroll
            for (int o = 16; o; o >>= 1) mx = fmaxf(mx, __shfl_xor_sync(0xffffffffu, mx, o));
            float e0 = v0 ? __expf(x0 - mx) : 0.f;
            float e1 = v1 ? __expf(x1 - mx) : 0.f;
            float ssum = e0 + e1;
#pragma unroll
            for (int o = 16; o; o >>= 1) ssum += __shfl_xor_sync(0xffffffffu, ssum, o);
            float inv = 1.0f / ssum;
            float* So = g_S + ((size_t)layer * BM + bm0 + bm) * T * T + (size_t)l * T;
            if (v0) So[e] = e0 * inv;
            if (v1) So[e + 32] = e1 * inv;
        }
    }
}

// ---------------- channel mean + expand (fused) ----------------
template <int T, int P, bool TILE>
__global__ __launch_bounds__(256) void mean_expand_kernel(float* __restrict__ out) {
    constexpr int TT = T * T;
    __shared__ float sA[TT];
    int b = blockIdx.x, layer = blockIdx.y;
    const float* Sb = g_S + ((size_t)layer * BM + (size_t)b * MN) * TT;
    for (int r = threadIdx.x; r < TT; r += 256) {
        float s = 0.f;
#pragma unroll 5
        for (int m = 0; m < MN; m++) s += Sb[(size_t)m * TT + r];
        sA[r] = s * (1.0f / MN);
    }
    __syncthreads();
    float* ob = out + ((size_t)layer * BN + b) * LL;
    for (int i = threadIdx.x; i < LL; i += 256) {
        int l = i / LN, s = i - l * LN;
        int al = TILE ? (l % P) : (l / P);
        int as = TILE ? (s % P) : (s / P);
        ob[i] = sA[al * T + as];
    }
}

// ---------------- host orchestration ----------------
template <int T, int C, int P, bool TILE>
static void run_branch(int woff, float* outbase) {
    conv_embed_kernel<T, C><<<BM, 256>>>(woff);
    constexpr int QB = (T < 16) ? (16 / T) : 1;
    constexpr int NB = (T < 16) ? (8 * QB) : (128 / T);
    int nblk = (BM + NB - 1) / NB;
    cudaFuncSetAttribute(fused_kernel<T>, cudaFuncAttributeMaxDynamicSharedMemorySize, FUSED_SMEM);
    fused_kernel<T><<<nblk, 512, FUSED_SMEM>>>();
    mean_expand_kernel<T, P, TILE><<<dim3(BN, ELN), 256>>>(outbase);
}

extern "C" void kernel_launch(void* const* d_in, const int* in_sizes, int n_in,
                              void* d_out, int out_size) {
    const float* x = (const float*)d_in[0];
    const float* Wq = (const float*)d_in[7];
    const float* bq = (const float*)d_in[8];
    const float* Wk = (const float*)d_in[9];
    const float* bk = (const float*)d_in[10];
    float* out = (float*)d_out;

    k1_kernel<<<1250, 256>>>(x, Wq, Wk, bq, bk,
                             (const float*)d_in[1], (const float*)d_in[2],
                             (const float*)d_in[3], (const float*)d_in[4],
                             (const float*)d_in[5], (const float*)d_in[6]);
    meffT_kernel<<<dim3(256, ELN), 256>>>();

    // branch order matches c_wcum: (35,3),(3,35),(21,5),(5,21),(15,7),(7,15)
    run_branch<35, 3, 3, false>(0, out + (size_t)0 * BN * LL);
    run_branch<3, 35, 3, true>(2304, out + (size_t)9 * BN * LL);
    run_branch<21, 5, 5, false>(29184, out + (size_t)3 * BN * LL);
    run_branch<5, 21, 5, true>(33024, out + (size_t)12 * BN * LL);
    run_branch<15, 7, 7, false>(49152, out + (size_t)6 * BN * LL);
    run_branch<7, 15, 7, true>(54528, out + (size_t)15 * BN * LL);
}

// round 9
// speedup vs baseline: 3.7852x; 1.0013x over previous
#include <cuda_runtime.h>
#include <cuda_fp16.h>
#include <math.h>
#include <cstdint>

#define BN 128
#define LN 105
#define MN 55
#define DN 256
#define ELN 3
static constexpr int BM = BN * MN;      // 7040
static constexpr int LL = LN * LN;      // 11025
static constexpr float SCALE = 0.0625f; // 1/sqrt(256)

// ---------------- scratch (device globals) ----------------
__device__ __align__(128) float g_xt[BM * LN];
__device__ __align__(128) __half g_zh[(size_t)BM * 35 * DN];       // fp16 Z
__device__ __align__(128) float g_wT[66048];                        // all branches
__device__ __align__(128) float g_meff[ELN * DN * DN];
__device__ __align__(128) __half g_mth[ELN * DN * DN];              // MeffT hi [n][k]
__device__ __align__(128) __half g_mtl[ELN * DN * DN];              // MeffT lo
__device__ float g_u[ELN * DN];
__device__ float g_v[ELN * DN];
__device__ float g_cc[ELN];
__device__ __align__(128) float g_S[(size_t)ELN * BM * 35 * 35];

// ---------------- helpers ----------------
__device__ __forceinline__ uint32_t smem_u32(const void* p) {
    uint32_t a;
    asm("{ .reg .u64 t; cvta.to.shared.u64 t, %1; cvt.u32.u64 %0, t; }" : "=r"(a) : "l"(p));
    return a;
}
__device__ __forceinline__ void cp_async16(uint32_t saddr, const void* gptr) {
    asm volatile("cp.async.ca.shared.global [%0], [%1], 16;" :: "r"(saddr), "l"(gptr) : "memory");
}
__device__ __forceinline__ void mma16816(float* d, const uint32_t* a, uint32_t b0, uint32_t b1) {
    asm volatile(
        "mma.sync.aligned.m16n8k16.row.col.f32.f16.f16.f32 "
        "{%0,%1,%2,%3}, {%4,%5,%6,%7}, {%8,%9}, {%0,%1,%2,%3};"
        : "+f"(d[0]), "+f"(d[1]), "+f"(d[2]), "+f"(d[3])
        : "r"(a[0]), "r"(a[1]), "r"(a[2]), "r"(a[3]), "r"(b0), "r"(b1));
}
#define LDMX4(r0, r1, r2, r3, addr) \
    asm volatile("ldmatrix.sync.aligned.m8n8.x4.shared.b16 {%0,%1,%2,%3}, [%4];" \
        : "=r"(r0), "=r"(r1), "=r"(r2), "=r"(r3) : "r"(addr))

// ---------------- K1: revin + meff + uvc + wtrans(all branches) ----------------
__constant__ int c_wcum[7] = {0, 2304, 29184, 33024, 49152, 54528, 66048};
__constant__ int c_wC[6] = {3, 35, 5, 21, 7, 15};

__global__ __launch_bounds__(256) void k1_kernel(
    const float* __restrict__ x,
    const float* __restrict__ Wq, const float* __restrict__ Wk,
    const float* __restrict__ bq, const float* __restrict__ bk,
    const float* __restrict__ w0, const float* __restrict__ w1,
    const float* __restrict__ w2, const float* __restrict__ w3,
    const float* __restrict__ w4, const float* __restrict__ w5) {
    int blk = blockIdx.x;
    int tid = threadIdx.x;
    if (blk < 128) {
        __shared__ float sx[LN * MN];
        __shared__ float smean[MN], sinv[MN];
        int b = blk;
        const float* xb = x + (size_t)b * LN * MN;
        for (int i = tid; i < LN * MN; i += 256) sx[i] = xb[i];
        __syncthreads();
        for (int m = tid; m < MN; m += 256) {
            float s = 0.f, s2 = 0.f;
            for (int l = 0; l < LN; l++) { float v = sx[l * MN + m]; s += v; s2 += v * v; }
            float mean = s * (1.0f / LN);
            float var = s2 * (1.0f / LN) - mean * mean;
            smean[m] = mean;
            sinv[m] = rsqrtf(var + 1e-5f);
        }
        __syncthreads();
        float* ob = g_xt + (size_t)b * MN * LN;
        for (int i = tid; i < MN * LN; i += 256) {
            int m = i / LN, l = i - m * LN;
            ob[i] = (sx[l * MN + m] - smean[m]) * sinv[m];
        }
    } else if (blk < 896) {
        __shared__ float sq[16][17], sk[16][17];
        int u = blk - 128;
        int l = u >> 8;
        int rem = u & 255;
        int i0 = (rem >> 4) * 16, j0 = (rem & 15) * 16;
        int ty = tid >> 4, tx = tid & 15;
        float acc = 0.f;
        const float* wq = Wq + (size_t)l * DN * DN;
        const float* wk = Wk + (size_t)l * DN * DN;
        for (int k0 = 0; k0 < DN; k0 += 16) {
            sq[ty][tx] = wq[(i0 + ty) * DN + k0 + tx];
            sk[ty][tx] = wk[(j0 + ty) * DN + k0 + tx];
            __syncthreads();
#pragma unroll
            for (int kk = 0; kk < 16; kk++) acc += sq[ty][kk] * sk[tx][kk];
            __syncthreads();
        }
        g_meff[(size_t)l * DN * DN + (i0 + ty) * DN + j0 + tx] = acc;
    } else if (blk < 992) {
        int u = blk - 896;
        int l = u >> 5, r = u & 31;
        int wid = tid >> 5, lane = tid & 31;
        int k = r * 8 + wid;
        float su = 0.f, sv = 0.f;
        const float* wq = Wq + (size_t)l * DN * DN + (size_t)k * DN;
        const float* wk = Wk + (size_t)l * DN * DN + (size_t)k * DN;
        for (int d = lane; d < DN; d += 32) {
            su += wq[d] * bk[l * DN + d];
            sv += wk[d] * bq[l * DN + d];
        }
#pragma unroll
        for (int o = 16; o; o >>= 1) {
            su += __shfl_xor_sync(0xffffffffu, su, o);
            sv += __shfl_xor_sync(0xffffffffu, sv, o);
        }
        if (lane == 0) {
            g_u[l * DN + k] = su;
            g_v[l * DN + k] = sv;
        }
        if (r == 0 && wid == 0) {
            float c = 0.f;
            for (int d = lane; d < DN; d += 32) c += bq[l * DN + d] * bk[l * DN + d];
#pragma unroll
            for (int o = 16; o; o >>= 1) c += __shfl_xor_sync(0xffffffffu, c, o);
            if (lane == 0) g_cc[l] = c;
        }
    } else {
        int i = (blk - 992) * 256 + tid;
        if (i < 66048) {
            int br = 0;
#pragma unroll
            for (int q = 1; q < 6; q++)
                if (i >= c_wcum[q]) br = q;
            const float* wp = br == 0 ? w0 : br == 1 ? w1 : br == 2 ? w2 : br == 3 ? w3 : br == 4 ? w4 : w5;
            int j = i - c_wcum[br];
            int C3 = c_wC[br] * 3;
            int d = j / C3, r = j - d * C3;
            g_wT[c_wcum[br] + r * DN + d] = wp[j];
        }
    }
}

// ---------------- meffT: fp16 hi/lo split of Meff^T ----------------
__global__ void meffT_kernel() {
    int l = blockIdx.y;
    int i = blockIdx.x * 256 + threadIdx.x;   // n*256+k
    int n = i >> 8, k = i & 255;
    float v = g_meff[(size_t)l * DN * DN + k * DN + n];
    __half h = __float2half_rn(v);
    g_mth[(size_t)l * DN * DN + i] = h;
    g_mtl[(size_t)l * DN * DN + i] = __float2half_rn(v - __half2float(h));
}

// ---------------- circular conv + PE -> Z (fp16) ----------------
template <int T, int C>
__global__ __launch_bounds__(256) void conv_embed_kernel(int woff) {
    constexpr int CHUNK = 8;
    __shared__ float sx[LN];
    __shared__ float sw[3 * CHUNK * DN];
    int bm = blockIdx.x;
    int d = threadIdx.x;
    for (int i = threadIdx.x; i < LN; i += blockDim.x) sx[i] = g_xt[(size_t)bm * LN + i];
    float acc[T];
#pragma unroll
    for (int t = 0; t < T; t++) acc[t] = 0.f;
    const float* wT = g_wT + woff;
    for (int c0 = 0; c0 < C; c0 += CHUNK) {
        int cw = (C - c0 < CHUNK) ? (C - c0) : CHUNK;
        __syncthreads();
        for (int i = threadIdx.x; i < cw * 3 * DN; i += blockDim.x)
            sw[i] = wT[c0 * 3 * DN + i];
        __syncthreads();
        for (int ci = 0; ci < cw; ci++) {
            int c = c0 + ci;
            float w0 = sw[(ci * 3 + 0) * DN + d];
            float w1 = sw[(ci * 3 + 1) * DN + d];
            float w2 = sw[(ci * 3 + 2) * DN + d];
#pragma unroll
            for (int t = 0; t < T; t++) {
                int tm = (t == 0) ? (T - 1) : (t - 1);
                int tp = (t == T - 1) ? 0 : (t + 1);
                acc[t] += w0 * sx[tm * C + c] + w1 * sx[t * C + c] + w2 * sx[tp * C + c];
            }
        }
    }
    float freq = expf(-(float)(2 * (d >> 1)) * (9.210340371976184f / 256.f));
    bool isodd = (d & 1);
#pragma unroll
    for (int t = 0; t < T; t++) {
        float arg = (float)t * freq;
        float pe = isodd ? cosf(arg) : sinf(arg);
        g_zh[((size_t)bm * T + t) * DN + d] = __float2half_rn(acc[t] + pe);
    }
}

// ---------------- fused: all 3 layers, G = Zh@(Mh+Ml), S = softmax((Gh+Gl)Zh^T+bias) --
static constexpr int OZH  = 0;        // Zh [128][256] fp16 (65536)
static constexpr int OGH  = 65536;    // Gh half [128][128] fp16 (32768)
static constexpr int OGL  = 98304;    // Gl half
static constexpr int OB0H = 131072;   // B buf0 hi (16384)
static constexpr int OB0L = 147456;   // B buf0 lo
static constexpr int OB1H = 163840;   // B buf1 hi
static constexpr int OB1L = 180224;   // B buf1 lo
static constexpr int OSS  = 131072;   // S overlay (reuses B0 region, <= 32KB)
static constexpr int OU   = 196608;   // u [3][256] f32 (3072)
static constexpr int OV   = 199680;   // v (3072)
static constexpr int OZU  = 202752;   // zu [3][128] (1536)
static constexpr int OZV  = 204288;   // zv (1536)
static constexpr int FUSED_SMEM = 205824;

template <int T>
__global__ __launch_bounds__(512, 1) void fused_kernel() {
    constexpr int MT = (T + 15) / 16;
    constexpr int QB = (T < 16) ? (16 / T) : 1;
    constexpr int NB = (T < 16) ? (8 * QB) : (128 / T);
    constexpr int NTILES = (T < 16) ? 8 : (NB * MT * MT);
    constexpr int TC = (T + 3) & ~3;
    constexpr int SLOTS = (NTILES + 15) / 16;

    extern __shared__ __align__(128) char smem[];
    const uint32_t sb = smem_u32(smem);
    const int tid = threadIdx.x;
    const int lane = tid & 31;
    const int wid = tid >> 5;
    const int bm0 = blockIdx.x * NB;
    const int nbm = min(NB, BM - bm0);
    const int nrows = nbm * T;

    // ---- load Z rows once (fp16), zero pad rows, stage u/v for all layers ----
    const __half* Zh = g_zh + (size_t)bm0 * T * DN;
    for (int idx = tid; idx < nrows * 32; idx += 512) {
        int r = idx >> 5, c = idx & 31;
        uint32_t off = r * 512 + ((c ^ (r & 7)) << 4);
        cp_async16(sb + OZH + off, Zh + (size_t)r * DN + c * 8);
    }
    asm volatile("cp.async.commit_group;" ::: "memory");
    for (int idx = tid + nrows * 32; idx < 128 * 32; idx += 512) {
        int r = idx >> 5, c = idx & 31;
        *(uint4*)(smem + OZH + r * 512 + (c << 4)) = make_uint4(0, 0, 0, 0);
    }
    for (int i = tid; i < 768; i += 512) {
        ((float*)(smem + OU))[i] = g_u[i];
        ((float*)(smem + OV))[i] = g_v[i];
    }
    asm volatile("cp.async.wait_group 0;" ::: "memory");
    __syncthreads();

    // ---- zu/zv per row for ALL 3 layers (4 threads per row) ----
    {
        int r = tid >> 2, p = tid & 3;
        float au[3] = {0.f, 0.f, 0.f}, av[3] = {0.f, 0.f, 0.f};
        if (r < nrows) {
            const float* su = (const float*)(smem + OU);
            const float* sv = (const float*)(smem + OV);
            for (int c = p * 8; c < p * 8 + 8; c++) {
                uint32_t off = r * 512 + ((c ^ (r & 7)) << 4);
                const __half* ph = (const __half*)(smem + OZH + off);
#pragma unroll
                for (int j = 0; j < 8; j++) {
                    float z = __half2float(ph[j]);
#pragma unroll
                    for (int l = 0; l < 3; l++) {
                        au[l] += z * su[l * DN + c * 8 + j];
                        av[l] += z * sv[l * DN + c * 8 + j];
                    }
                }
            }
        }
#pragma unroll
        for (int l = 0; l < 3; l++) {
            au[l] += __shfl_xor_sync(0xffffffffu, au[l], 1);
            au[l] += __shfl_xor_sync(0xffffffffu, au[l], 2);
            av[l] += __shfl_xor_sync(0xffffffffu, av[l], 1);
            av[l] += __shfl_xor_sync(0xffffffffu, av[l], 2);
        }
        if (p == 0 && r < nrows) {
#pragma unroll
            for (int l = 0; l < 3; l++) {
                ((float*)(smem + OZU))[l * 128 + r] = au[l];
                ((float*)(smem + OZV))[l * 128 + r] = av[l];
            }
        }
    }

    const int wm = wid >> 2, wn = wid & 3;
    const int rA = lane & 15;
    const int chsel = lane >> 4;
    const int brr = tid >> 3, bcc = tid & 7;
    const uint32_t boff = brr * 128 + ((bcc ^ (brr & 7)) << 4);
    const uint32_t boff2 = (brr + 64) * 128 + ((bcc ^ ((brr + 64) & 7)) << 4);

// async stage of B chunk (hi+lo) into buffer `buf` for k-chunk `kc`
#define STAGE_B(kc, buf)                                                           \
    do {                                                                           \
        const __half* bh_ = Bh_src + (size_t)(h * 128) * DN + (kc) * 64;           \
        const __half* bl_ = Bl_src + (size_t)(h * 128) * DN + (kc) * 64;           \
        uint32_t dh_ = sb + ((buf) ? OB1H : OB0H);                                 \
        uint32_t dl_ = sb + ((buf) ? OB1L : OB0L);                                 \
        cp_async16(dh_ + boff, bh_ + (size_t)brr * DN + bcc * 8);                  \
        cp_async16(dh_ + boff2, bh_ + (size_t)(brr + 64) * DN + bcc * 8);          \
        cp_async16(dl_ + boff, bl_ + (size_t)brr * DN + bcc * 8);                  \
        cp_async16(dl_ + boff2, bl_ + (size_t)(brr + 64) * DN + bcc * 8);          \
        asm volatile("cp.async.commit_group;" ::: "memory");                       \
    } while (0)

    for (int layer = 0; layer < ELN; layer++) {
        __syncthreads();  // prior layer's softmax done reading sS (overlaid on B0)

        float sfr[SLOTS][2][4];
#pragma unroll
        for (int s = 0; s < SLOTS; s++)
#pragma unroll
            for (int j = 0; j < 2; j++)
#pragma unroll
                for (int q = 0; q < 4; q++) sfr[s][j][q] = 0.f;

        const __half* Bh_src = g_mth + (size_t)layer * DN * DN;
        const __half* Bl_src = g_mtl + (size_t)layer * DN * DN;

        for (int h = 0; h < 2; h++) {
            float acc[2][4][4];
#pragma unroll
            for (int mt = 0; mt < 2; mt++)
#pragma unroll
                for (int j = 0; j < 4; j++)
#pragma unroll
                    for (int q = 0; q < 4; q++) acc[mt][j][q] = 0.f;

            STAGE_B(0, 0);
            for (int kc = 0; kc < 4; kc++) {
                asm volatile("cp.async.wait_group 0;" ::: "memory");
                __syncthreads();                       // stage(kc) visible; prev buf free
                if (kc < 3) STAGE_B(kc + 1, (kc + 1) & 1);
                uint32_t sBH = sb + ((kc & 1) ? OB1H : OB0H);
#pragma unroll
                for (int ks = 0; ks < 4; ks++) {
                    int chA = kc * 8 + ks * 2 + chsel;
                    uint32_t ah[2][4];
#pragma unroll
                    for (int mt = 0; mt < 2; mt++) {
                        int row = wm * 32 + mt * 16 + rA;
                        uint32_t ad = sb + OZH + row * 512 + ((chA ^ (row & 7)) << 4);
                        LDMX4(ah[mt][0], ah[mt][1], ah[mt][2], ah[mt][3], ad);
                    }
                    uint32_t bh[2][4], bl[2][4];
#pragma unroll
                    for (int ng = 0; ng < 2; ng++) {
                        int row = wn * 32 + ng * 16 + rA;
                        uint32_t bd = sBH + row * 128 + (((ks * 2 + chsel) ^ (row & 7)) << 4);
                        LDMX4(bh[ng][0], bh[ng][1], bh[ng][2], bh[ng][3], bd);
                        LDMX4(bl[ng][0], bl[ng][1], bl[ng][2], bl[ng][3], bd + 16384);
                    }
#pragma unroll
                    for (int mt = 0; mt < 2; mt++)
#pragma unroll
                        for (int ng = 0; ng < 2; ng++) {
                            mma16816(acc[mt][ng * 2 + 0], ah[mt], bh[ng][0], bh[ng][2]);
                            mma16816(acc[mt][ng * 2 + 1], ah[mt], bh[ng][1], bh[ng][3]);
                            mma16816(acc[mt][ng * 2 + 0], ah[mt], bl[ng][0], bl[ng][2]);
                            mma16816(acc[mt][ng * 2 + 1], ah[mt], bl[ng][1], bl[ng][3]);
                        }
                }
            }
            __syncthreads();
            // G accum -> fp16 hi/lo smem
#pragma unroll
            for (int mt = 0; mt < 2; mt++)
#pragma unroll
                for (int j = 0; j < 4; j++) {
                    int c = wn * 32 + (j >> 1) * 16 + (j & 1) * 8 + (lane & 3) * 2;
#pragma unroll
                    for (int half = 0; half < 2; half++) {
                        int r = wm * 32 + mt * 16 + (lane >> 2) + half * 8;
                        float v0 = acc[mt][j][half * 2 + 0];
                        float v1 = acc[mt][j][half * 2 + 1];
                        uint32_t off = r * 256 + ((((c >> 3)) ^ (r & 7)) << 4) + (c & 7) * 2;
                        __half h0 = __float2half_rn(v0);
                        __half h1 = __float2half_rn(v1);
                        *(__half2*)(smem + OGH + off) = __half2(h0, h1);
                        __half l0 = __float2half_rn(v0 - __half2float(h0));
                        __half l1 = __float2half_rn(v1 - __half2float(h1));
                        *(__half2*)(smem + OGL + off) = __half2(l0, l1);
                    }
                }
            __syncthreads();
            // phase2: S += (Gh+Gl) @ Zh_half^T on diagonal tiles
            int slot = 0;
            for (int t = wid; t < NTILES; t += 16, slot++) {
                int rb, cb;
                if (T < 16) {
                    rb = cb = t * QB * T;
                } else {
                    int tbm = t / (MT * MT);
                    int rem = t % (MT * MT);
                    rb = tbm * T + (rem / MT) * 16;
                    cb = tbm * T + (rem % MT) * 16;
                }
#pragma unroll
                for (int kc = 0; kc < 8; kc++) {
                    int ch = kc * 2 + chsel;
                    int arow = rb + rA;
                    uint32_t aad = sb + OGH + arow * 256 + ((ch ^ (arow & 7)) << 4);
                    uint32_t gh[4], gl[4];
                    LDMX4(gh[0], gh[1], gh[2], gh[3], aad);
                    LDMX4(gl[0], gl[1], gl[2], gl[3], aad + 32768);
                    int brow = cb + rA;
                    int chz = h * 16 + ch;
                    uint32_t bad = sb + OZH + brow * 512 + ((chz ^ (brow & 7)) << 4);
                    uint32_t zh2[4];
                    LDMX4(zh2[0], zh2[1], zh2[2], zh2[3], bad);
                    mma16816(sfr[slot][0], gh, zh2[0], zh2[2]);
                    mma16816(sfr[slot][1], gh, zh2[1], zh2[3]);
                    mma16816(sfr[slot][0], gl, zh2[0], zh2[2]);
                    mma16816(sfr[slot][1], gl, zh2[1], zh2[3]);
                }
            }
        }
        __syncthreads();

        // ---- S frags -> smem overlay ----
        float* sS = (float*)(smem + OSS);
        {
            int slot = 0;
            for (int t = wid; t < NTILES; t += 16, slot++) {
                int tbm = -1, ti = 0, tj = 0;
                if (T >= 16) {
                    tbm = t / (MT * MT);
                    int rem = t % (MT * MT);
                    ti = rem / MT;
                    tj = rem % MT;
                }
                int fr = lane >> 2, fc = (lane & 3) * 2;
#pragma unroll
                for (int j = 0; j < 2; j++)
#pragma unroll
                    for (int q = 0; q < 4; q++) {
                        int rr = fr + (q >> 1) * 8;
                        int cc = fc + (q & 1) + j * 8;
                        float v = sfr[slot][j][q];
                        if (T < 16) {
                            int qr = rr / T, qc = cc / T;
                            if (qr == qc && qr < QB) {
                                int bm = t * QB + qr;
                                if (bm < nbm) sS[(bm * T + rr - qr * T) * TC + (cc - qc * T)] = v;
                            }
                        } else {
                            if (tbm < nbm && ti * 16 + rr < T && tj * 16 + cc < T)
                                sS[(tbm * T + ti * 16 + rr) * TC + tj * 16 + cc] = v;
                        }
                    }
            }
        }
        __syncthreads();

        // ---- softmax rows -> g_S ----
        float cterm = g_cc[layer];
        const float* zu = (const float*)(smem + OZU) + layer * 128;
        const float* zv = (const float*)(smem + OZV) + layer * 128;
        int e = lane;
        for (int rho = wid; rho < nrows; rho += 16) {
            int bm = rho / T, l = rho % T;
            const float* row = sS + (bm * T + l) * TC;
            bool v0 = (e < T);
            bool v1 = (T > 32) && (e + 32 < T);
            float zul = zu[rho];
            float x0 = v0 ? SCALE * (row[e] + zul + zv[bm * T + e] + cterm) : -1e30f;
            float x1 = v1 ? SCALE * (row[e + 32] + zul + zv[bm * T + e + 32] + cterm) : -1e30f;
            float mx = fmaxf(x0, x1);
#pragma unroll
            for (int o = 16; o; o >>= 1) mx = fmaxf(mx, __shfl_xor_sync(0xffffffffu, mx, o));
            float e0 = v0 ? __expf(x0 - mx) : 0.f;
            float e1 = v1 ? __expf(x1 - mx) : 0.f;
            float ssum = e0 + e1;
#pragma unroll
            for (int o = 16; o; o >>= 1) ssum += __shfl_xor_sync(0xffffffffu, ssum, o);
            float inv = 1.0f / ssum;
            float* So = g_S + ((size_t)layer * BM + bm0 + bm) * T * T + (size_t)l * T;
            if (v0) So[e] = e0 * inv;
            if (v1) So[e + 32] = e1 * inv;
        }
    }
#undef STAGE_B
}

// ---------------- channel mean + expand (fused) ----------------
template <int T, int P, bool TILE>
__global__ __launch_bounds__(256) void mean_expand_kernel(float* __restrict__ out) {
    constexpr int TT = T * T;
    __shared__ float sA[TT];
    int b = blockIdx.x, layer = blockIdx.y;
    const float* Sb = g_S + ((size_t)layer * BM + (size_t)b * MN) * TT;
    for (int r = threadIdx.x; r < TT; r += 256) {
        float s = 0.f;
#pragma unroll 5
        for (int m = 0; m < MN; m++) s += Sb[(size_t)m * TT + r];
        sA[r] = s * (1.0f / MN);
    }
    __syncthreads();
    float* ob = out + ((size_t)layer * BN + b) * LL;
    for (int i = threadIdx.x; i < LL; i += 256) {
        int l = i / LN, s = i - l * LN;
        int al = TILE ? (l % P) : (l / P);
        int as = TILE ? (s % P) : (s / P);
        ob[i] = sA[al * T + as];
    }
}

// ---------------- host orchestration ----------------
template <int T, int C, int P, bool TILE>
static void run_branch(int woff, float* outbase) {
    conv_embed_kernel<T, C><<<BM, 256>>>(woff);
    constexpr int QB = (T < 16) ? (16 / T) : 1;
    constexpr int NB = (T < 16) ? (8 * QB) : (128 / T);
    int nblk = (BM + NB - 1) / NB;
    cudaFuncSetAttribute(fused_kernel<T>, cudaFuncAttributeMaxDynamicSharedMemorySize, FUSED_SMEM);
    fused_kernel<T><<<nblk, 512, FUSED_SMEM>>>();
    mean_expand_kernel<T, P, TILE><<<dim3(BN, ELN), 256>>>(outbase);
}

extern "C" void kernel_launch(void* const* d_in, const int* in_sizes, int n_in,
                              void* d_out, int out_size) {
    const float* x = (const float*)d_in[0];
    const float* Wq = (const float*)d_in[7];
    const float* bq = (const float*)d_in[8];
    const float* Wk = (const float*)d_in[9];
    const float* bk = (const float*)d_in[10];
    float* out = (float*)d_out;

    k1_kernel<<<1250, 256>>>(x, Wq, Wk, bq, bk,
                             (const float*)d_in[1], (const float*)d_in[2],
                             (const float*)d_in[3], (const float*)d_in[4],
                             (const float*)d_in[5], (const float*)d_in[6]);
    meffT_kernel<<<dim3(256, ELN), 256>>>();

    run_branch<35, 3, 3, false>(0, out + (size_t)0 * BN * LL);
    run_branch<3, 35, 3, true>(2304, out + (size_t)9 * BN * LL);
    run_branch<21, 5, 5, false>(29184, out + (size_t)3 * BN * LL);
    run_branch<5, 21, 5, true>(33024, out + (size_t)12 * BN * LL);
    run_branch<15, 7, 7, false>(49152, out + (size_t)6 * BN * LL);
    run_branch<7, 15, 7, true>(54528, out + (size_t)15 * BN * LL);
}

// round 10
// speedup vs baseline: 5.0171x; 1.3255x over previous
#include <cuda_runtime.h>
#include <cuda_fp16.h>
#include <math.h>
#include <cstdint>

#define BN 128
#define LN 105
#define MN 55
#define DN 256
#define ELN 3
static constexpr int BM = BN * MN;      // 7040
static constexpr int LL = LN * LN;      // 11025
static constexpr float SCALE = 0.0625f; // 1/sqrt(256)

// ---------------- scratch (device globals) ----------------
__device__ __align__(128) float g_xt[BM * LN];
__device__ __align__(128) __half g_zh[(size_t)BM * 35 * DN];       // fp16 Z
__device__ __align__(128) float g_wT[66048];                        // all branches
__device__ __align__(128) float g_meff[ELN * DN * DN];
__device__ __align__(128) __half g_mth[ELN * DN * DN];              // MeffT [n][k] fp16
__device__ float g_u[ELN * DN];
__device__ float g_v[ELN * DN];
__device__ float g_cc[ELN];
__device__ __align__(128) float g_S[(size_t)ELN * BM * 35 * 35];

// ---------------- helpers ----------------
__device__ __forceinline__ uint32_t smem_u32(const void* p) {
    uint32_t a;
    asm("{ .reg .u64 t; cvta.to.shared.u64 t, %1; cvt.u32.u64 %0, t; }" : "=r"(a) : "l"(p));
    return a;
}
__device__ __forceinline__ void cp_async16(uint32_t saddr, const void* gptr) {
    asm volatile("cp.async.ca.shared.global [%0], [%1], 16;" :: "r"(saddr), "l"(gptr) : "memory");
}
__device__ __forceinline__ void mma16816(float* d, const uint32_t* a, uint32_t b0, uint32_t b1) {
    asm volatile(
        "mma.sync.aligned.m16n8k16.row.col.f32.f16.f16.f32 "
        "{%0,%1,%2,%3}, {%4,%5,%6,%7}, {%8,%9}, {%0,%1,%2,%3};"
        : "+f"(d[0]), "+f"(d[1]), "+f"(d[2]), "+f"(d[3])
        : "r"(a[0]), "r"(a[1]), "r"(a[2]), "r"(a[3]), "r"(b0), "r"(b1));
}
#define LDMX4(r0, r1, r2, r3, addr) \
    asm volatile("ldmatrix.sync.aligned.m8n8.x4.shared.b16 {%0,%1,%2,%3}, [%4];" \
        : "=r"(r0), "=r"(r1), "=r"(r2), "=r"(r3) : "r"(addr))

// ---------------- K1: revin + meff + uvc + wtrans(all branches) ----------------
__constant__ int c_wcum[7] = {0, 2304, 29184, 33024, 49152, 54528, 66048};
__constant__ int c_wC[6] = {3, 35, 5, 21, 7, 15};

__global__ __launch_bounds__(256) void k1_kernel(
    const float* __restrict__ x,
    const float* __restrict__ Wq, const float* __restrict__ Wk,
    const float* __restrict__ bq, const float* __restrict__ bk,
    const float* __restrict__ w0, const float* __restrict__ w1,
    const float* __restrict__ w2, const float* __restrict__ w3,
    const float* __restrict__ w4, const float* __restrict__ w5) {
    int blk = blockIdx.x;
    int tid = threadIdx.x;
    if (blk < 128) {
        __shared__ float sx[LN * MN];
        __shared__ float smean[MN], sinv[MN];
        int b = blk;
        const float* xb = x + (size_t)b * LN * MN;
        for (int i = tid; i < LN * MN; i += 256) sx[i] = xb[i];
        __syncthreads();
        for (int m = tid; m < MN; m += 256) {
            float s = 0.f, s2 = 0.f;
            for (int l = 0; l < LN; l++) { float v = sx[l * MN + m]; s += v; s2 += v * v; }
            float mean = s * (1.0f / LN);
            float var = s2 * (1.0f / LN) - mean * mean;
            smean[m] = mean;
            sinv[m] = rsqrtf(var + 1e-5f);
        }
        __syncthreads();
        float* ob = g_xt + (size_t)b * MN * LN;
        for (int i = tid; i < MN * LN; i += 256) {
            int m = i / LN, l = i - m * LN;
            ob[i] = (sx[l * MN + m] - smean[m]) * sinv[m];
        }
    } else if (blk < 896) {
        __shared__ float sq[16][17], sk[16][17];
        int u = blk - 128;
        int l = u >> 8;
        int rem = u & 255;
        int i0 = (rem >> 4) * 16, j0 = (rem & 15) * 16;
        int ty = tid >> 4, tx = tid & 15;
        float acc = 0.f;
        const float* wq = Wq + (size_t)l * DN * DN;
        const float* wk = Wk + (size_t)l * DN * DN;
        for (int k0 = 0; k0 < DN; k0 += 16) {
            sq[ty][tx] = wq[(i0 + ty) * DN + k0 + tx];
            sk[ty][tx] = wk[(j0 + ty) * DN + k0 + tx];
            __syncthreads();
#pragma unroll
            for (int kk = 0; kk < 16; kk++) acc += sq[ty][kk] * sk[tx][kk];
            __syncthreads();
        }
        g_meff[(size_t)l * DN * DN + (i0 + ty) * DN + j0 + tx] = acc;
    } else if (blk < 992) {
        int u = blk - 896;
        int l = u >> 5, r = u & 31;
        int wid = tid >> 5, lane = tid & 31;
        int k = r * 8 + wid;
        float su = 0.f, sv = 0.f;
        const float* wq = Wq + (size_t)l * DN * DN + (size_t)k * DN;
        const float* wk = Wk + (size_t)l * DN * DN + (size_t)k * DN;
        for (int d = lane; d < DN; d += 32) {
            su += wq[d] * bk[l * DN + d];
            sv += wk[d] * bq[l * DN + d];
        }
#pragma unroll
        for (int o = 16; o; o >>= 1) {
            su += __shfl_xor_sync(0xffffffffu, su, o);
            sv += __shfl_xor_sync(0xffffffffu, sv, o);
        }
        if (lane == 0) {
            g_u[l * DN + k] = su;
            g_v[l * DN + k] = sv;
        }
        if (r == 0 && wid == 0) {
            float c = 0.f;
            for (int d = lane; d < DN; d += 32) c += bq[l * DN + d] * bk[l * DN + d];
#pragma unroll
            for (int o = 16; o; o >>= 1) c += __shfl_xor_sync(0xffffffffu, c, o);
            if (lane == 0) g_cc[l] = c;
        }
    } else {
        int i = (blk - 992) * 256 + tid;
        if (i < 66048) {
            int br = 0;
#pragma unroll
            for (int q = 1; q < 6; q++)
                if (i >= c_wcum[q]) br = q;
            const float* wp = br == 0 ? w0 : br == 1 ? w1 : br == 2 ? w2 : br == 3 ? w3 : br == 4 ? w4 : w5;
            int j = i - c_wcum[br];
            int C3 = c_wC[br] * 3;
            int d = j / C3, r = j - d * C3;
            g_wT[c_wcum[br] + r * DN + d] = wp[j];
        }
    }
}

// ---------------- meffT: fp16 Meff^T ----------------
__global__ void meffT_kernel() {
    int l = blockIdx.y;
    int i = blockIdx.x * 256 + threadIdx.x;   // n*256+k
    int n = i >> 8, k = i & 255;
    float v = g_meff[(size_t)l * DN * DN + k * DN + n];
    g_mth[(size_t)l * DN * DN + i] = __float2half_rn(v);
}

// ---------------- circular conv + PE -> Z (fp16) ----------------
template <int T, int C>
__global__ __launch_bounds__(256) void conv_embed_kernel(int woff) {
    constexpr int CHUNK = 8;
    __shared__ float sx[LN];
    __shared__ float sw[3 * CHUNK * DN];
    int bm = blockIdx.x;
    int d = threadIdx.x;
    for (int i = threadIdx.x; i < LN; i += blockDim.x) sx[i] = g_xt[(size_t)bm * LN + i];
    float acc[T];
#pragma unroll
    for (int t = 0; t < T; t++) acc[t] = 0.f;
    const float* wT = g_wT + woff;
    for (int c0 = 0; c0 < C; c0 += CHUNK) {
        int cw = (C - c0 < CHUNK) ? (C - c0) : CHUNK;
        __syncthreads();
        for (int i = threadIdx.x; i < cw * 3 * DN; i += blockDim.x)
            sw[i] = wT[c0 * 3 * DN + i];
        __syncthreads();
        for (int ci = 0; ci < cw; ci++) {
            int c = c0 + ci;
            float w0 = sw[(ci * 3 + 0) * DN + d];
            float w1 = sw[(ci * 3 + 1) * DN + d];
            float w2 = sw[(ci * 3 + 2) * DN + d];
#pragma unroll
            for (int t = 0; t < T; t++) {
                int tm = (t == 0) ? (T - 1) : (t - 1);
                int tp = (t == T - 1) ? 0 : (t + 1);
                acc[t] += w0 * sx[tm * C + c] + w1 * sx[t * C + c] + w2 * sx[tp * C + c];
            }
        }
    }
    float freq = expf(-(float)(2 * (d >> 1)) * (9.210340371976184f / 256.f));
    bool isodd = (d & 1);
#pragma unroll
    for (int t = 0; t < T; t++) {
        float arg = (float)t * freq;
        float pe = isodd ? cosf(arg) : sinf(arg);
        g_zh[((size_t)bm * T + t) * DN + d] = __float2half_rn(acc[t] + pe);
    }
}

// ---------------- fused: all 3 layers, G = Zh@Mh, S = softmax(Gh Zh^T + bias) ----
static constexpr int OZH  = 0;        // Zh [128][256] fp16 (65536)
static constexpr int OGH  = 65536;    // Gh half [128][128] fp16 (32768)
static constexpr int OB0H = 98304;    // B buf0 (16384)
static constexpr int OB1H = 114688;   // B buf1 (16384)
static constexpr int OSS  = 98304;    // S overlay (reuses B region, <= 32KB)
static constexpr int OU   = 131072;   // u [3][256] f32 (3072)
static constexpr int OV   = 134144;   // v (3072)
static constexpr int OZU  = 137216;   // zu [3][128] (1536)
static constexpr int OZV  = 138752;   // zv (1536)
static constexpr int FUSED_SMEM = 140288;

template <int T>
__global__ __launch_bounds__(512, 1) void fused_kernel() {
    constexpr int MT = (T + 15) / 16;
    constexpr int QB = (T < 16) ? (16 / T) : 1;
    constexpr int NB = (T < 16) ? (8 * QB) : (128 / T);
    constexpr int NTILES = (T < 16) ? 8 : (NB * MT * MT);
    constexpr int TC = (T + 3) & ~3;
    constexpr int SLOTS = (NTILES + 15) / 16;

    extern __shared__ __align__(128) char smem[];
    const uint32_t sb = smem_u32(smem);
    const int tid = threadIdx.x;
    const int lane = tid & 31;
    const int wid = tid >> 5;
    const int bm0 = blockIdx.x * NB;
    const int nbm = min(NB, BM - bm0);
    const int nrows = nbm * T;

    // ---- load Z rows once (fp16), zero pad rows, stage u/v for all layers ----
    const __half* Zh = g_zh + (size_t)bm0 * T * DN;
    for (int idx = tid; idx < nrows * 32; idx += 512) {
        int r = idx >> 5, c = idx & 31;
        uint32_t off = r * 512 + ((c ^ (r & 7)) << 4);
        cp_async16(sb + OZH + off, Zh + (size_t)r * DN + c * 8);
    }
    asm volatile("cp.async.commit_group;" ::: "memory");
    for (int idx = tid + nrows * 32; idx < 128 * 32; idx += 512) {
        int r = idx >> 5, c = idx & 31;
        *(uint4*)(smem + OZH + r * 512 + (c << 4)) = make_uint4(0, 0, 0, 0);
    }
    for (int i = tid; i < 768; i += 512) {
        ((float*)(smem + OU))[i] = g_u[i];
        ((float*)(smem + OV))[i] = g_v[i];
    }
    asm volatile("cp.async.wait_group 0;" ::: "memory");
    __syncthreads();

    // ---- zu/zv per row for ALL 3 layers (4 threads per row) ----
    {
        int r = tid >> 2, p = tid & 3;
        float au[3] = {0.f, 0.f, 0.f}, av[3] = {0.f, 0.f, 0.f};
        if (r < nrows) {
            const float* su = (const float*)(smem + OU);
            const float* sv = (const float*)(smem + OV);
            for (int c = p * 8; c < p * 8 + 8; c++) {
                uint32_t off = r * 512 + ((c ^ (r & 7)) << 4);
                const __half* ph = (const __half*)(smem + OZH + off);
#pragma unroll
                for (int j = 0; j < 8; j++) {
                    float z = __half2float(ph[j]);
#pragma unroll
                    for (int l = 0; l < 3; l++) {
                        au[l] += z * su[l * DN + c * 8 + j];
                        av[l] += z * sv[l * DN + c * 8 + j];
                    }
                }
            }
        }
#pragma unroll
        for (int l = 0; l < 3; l++) {
            au[l] += __shfl_xor_sync(0xffffffffu, au[l], 1);
            au[l] += __shfl_xor_sync(0xffffffffu, au[l], 2);
            av[l] += __shfl_xor_sync(0xffffffffu, av[l], 1);
            av[l] += __shfl_xor_sync(0xffffffffu, av[l], 2);
        }
        if (p == 0 && r < nrows) {
#pragma unroll
            for (int l = 0; l < 3; l++) {
                ((float*)(smem + OZU))[l * 128 + r] = au[l];
                ((float*)(smem + OZV))[l * 128 + r] = av[l];
            }
        }
    }

    const int wm = wid >> 2, wn = wid & 3;
    const int rA = lane & 15;
    const int chsel = lane >> 4;
    const int brr = tid >> 3, bcc = tid & 7;
    const uint32_t boff = brr * 128 + ((bcc ^ (brr & 7)) << 4);
    const uint32_t boff2 = (brr + 64) * 128 + ((bcc ^ ((brr + 64) & 7)) << 4);

#define STAGE_B(kc, buf)                                                           \
    do {                                                                           \
        const __half* bh_ = Bh_src + (size_t)(h * 128) * DN + (kc) * 64;           \
        uint32_t dh_ = sb + ((buf) ? OB1H : OB0H);                                 \
        cp_async16(dh_ + boff, bh_ + (size_t)brr * DN + bcc * 8);                  \
        cp_async16(dh_ + boff2, bh_ + (size_t)(brr + 64) * DN + bcc * 8);          \
        asm volatile("cp.async.commit_group;" ::: "memory");                       \
    } while (0)

    for (int layer = 0; layer < ELN; layer++) {
        __syncthreads();  // prior layer's softmax done reading sS (overlaid on B)

        float sfr[SLOTS][2][4];
#pragma unroll
        for (int s = 0; s < SLOTS; s++)
#pragma unroll
            for (int j = 0; j < 2; j++)
#pragma unroll
                for (int q = 0; q < 4; q++) sfr[s][j][q] = 0.f;

        const __half* Bh_src = g_mth + (size_t)layer * DN * DN;

        for (int h = 0; h < 2; h++) {
            float acc[2][4][4];
#pragma unroll
            for (int mt = 0; mt < 2; mt++)
#pragma unroll
                for (int j = 0; j < 4; j++)
#pragma unroll
                    for (int q = 0; q < 4; q++) acc[mt][j][q] = 0.f;

            STAGE_B(0, 0);
            for (int kc = 0; kc < 4; kc++) {
                asm volatile("cp.async.wait_group 0;" ::: "memory");
                __syncthreads();
                if (kc < 3) STAGE_B(kc + 1, (kc + 1) & 1);
                uint32_t sBH = sb + ((kc & 1) ? OB1H : OB0H);
#pragma unroll
                for (int ks = 0; ks < 4; ks++) {
                    int chA = kc * 8 + ks * 2 + chsel;
                    uint32_t ah[2][4];
#pragma unroll
                    for (int mt = 0; mt < 2; mt++) {
                        int row = wm * 32 + mt * 16 + rA;
                        uint32_t ad = sb + OZH + row * 512 + ((chA ^ (row & 7)) << 4);
                        LDMX4(ah[mt][0], ah[mt][1], ah[mt][2], ah[mt][3], ad);
                    }
                    uint32_t bh[2][4];
#pragma unroll
                    for (int ng = 0; ng < 2; ng++) {
                        int row = wn * 32 + ng * 16 + rA;
                        uint32_t bd = sBH + row * 128 + (((ks * 2 + chsel) ^ (row & 7)) << 4);
                        LDMX4(bh[ng][0], bh[ng][1], bh[ng][2], bh[ng][3], bd);
                    }
#pragma unroll
                    for (int mt = 0; mt < 2; mt++)
#pragma unroll
                        for (int ng = 0; ng < 2; ng++) {
                            mma16816(acc[mt][ng * 2 + 0], ah[mt], bh[ng][0], bh[ng][2]);
                            mma16816(acc[mt][ng * 2 + 1], ah[mt], bh[ng][1], bh[ng][3]);
                        }
                }
            }
            __syncthreads();
            // G accum -> fp16 smem
#pragma unroll
            for (int mt = 0; mt < 2; mt++)
#pragma unroll
                for (int j = 0; j < 4; j++) {
                    int c = wn * 32 + (j >> 1) * 16 + (j & 1) * 8 + (lane & 3) * 2;
#pragma unroll
                    for (int half = 0; half < 2; half++) {
                        int r = wm * 32 + mt * 16 + (lane >> 2) + half * 8;
                        float v0 = acc[mt][j][half * 2 + 0];
                        float v1 = acc[mt][j][half * 2 + 1];
                        uint32_t off = r * 256 + ((((c >> 3)) ^ (r & 7)) << 4) + (c & 7) * 2;
                        *(__half2*)(smem + OGH + off) = __half2(__float2half_rn(v0), __float2half_rn(v1));
                    }
                }
            __syncthreads();
            // phase2: S += Gh @ Zh_half^T on diagonal tiles
            int slot = 0;
            for (int t = wid; t < NTILES; t += 16, slot++) {
                int rb, cb;
                if (T < 16) {
                    rb = cb = t * QB * T;
                } else {
                    int tbm = t / (MT * MT);
                    int rem = t % (MT * MT);
                    rb = tbm * T + (rem / MT) * 16;
                    cb = tbm * T + (rem % MT) * 16;
                }
#pragma unroll
                for (int kc = 0; kc < 8; kc++) {
                    int ch = kc * 2 + chsel;
                    int arow = rb + rA;
                    uint32_t aad = sb + OGH + arow * 256 + ((ch ^ (arow & 7)) << 4);
                    uint32_t gh[4];
                    LDMX4(gh[0], gh[1], gh[2], gh[3], aad);
                    int brow = cb + rA;
                    int chz = h * 16 + ch;
                    uint32_t bad = sb + OZH + brow * 512 + ((chz ^ (brow & 7)) << 4);
                    uint32_t zh2[4];
                    LDMX4(zh2[0], zh2[1], zh2[2], zh2[3], bad);
                    mma16816(sfr[slot][0], gh, zh2[0], zh2[2]);
                    mma16816(sfr[slot][1], gh, zh2[1], zh2[3]);
                }
            }
        }
        __syncthreads();

        // ---- S frags -> smem overlay ----
        float* sS = (float*)(smem + OSS);
        {
            int slot = 0;
            for (int t = wid; t < NTILES; t += 16, slot++) {
                int tbm = -1, ti = 0, tj = 0;
                if (T >= 16) {
                    tbm = t / (MT * MT);
                    int rem = t % (MT * MT);
                    ti = rem / MT;
                    tj = rem % MT;
                }
                int fr = lane >> 2, fc = (lane & 3) * 2;
#pragma unroll
                for (int j = 0; j < 2; j++)
#pragma unroll
                    for (int q = 0; q < 4; q++) {
                        int rr = fr + (q >> 1) * 8;
                        int cc = fc + (q & 1) + j * 8;
                        float v = sfr[slot][j][q];
                        if (T < 16) {
                            int qr = rr / T, qc = cc / T;
                            if (qr == qc && qr < QB) {
                                int bm = t * QB + qr;
                                if (bm < nbm) sS[(bm * T + rr - qr * T) * TC + (cc - qc * T)] = v;
                            }
                        } else {
                            if (tbm < nbm && ti * 16 + rr < T && tj * 16 + cc < T)
                                sS[(tbm * T + ti * 16 + rr) * TC + tj * 16 + cc] = v;
                        }
                    }
            }
        }
        __syncthreads();

        // ---- softmax rows -> g_S ----
        float cterm = g_cc[layer];
        const float* zu = (const float*)(smem + OZU) + layer * 128;
        const float* zv = (const float*)(smem + OZV) + layer * 128;
        int e = lane;
        for (int rho = wid; rho < nrows; rho += 16) {
            int bm = rho / T, l = rho % T;
            const float* row = sS + (bm * T + l) * TC;
            bool v0 = (e < T);
            bool v1 = (T > 32) && (e + 32 < T);
            float zul = zu[rho];
            float x0 = v0 ? SCALE * (row[e] + zul + zv[bm * T + e] + cterm) : -1e30f;
            float x1 = v1 ? SCALE * (row[e + 32] + zul + zv[bm * T + e + 32] + cterm) : -1e30f;
            float mx = fmaxf(x0, x1);
#pragma unroll
            for (int o = 16; o; o >>= 1) mx = fmaxf(mx, __shfl_xor_sync(0xffffffffu, mx, o));
            float e0 = v0 ? __expf(x0 - mx) : 0.f;
            float e1 = v1 ? __expf(x1 - mx) : 0.f;
            float ssum = e0 + e1;
#pragma unroll
            for (int o = 16; o; o >>= 1) ssum += __shfl_xor_sync(0xffffffffu, ssum, o);
            float inv = 1.0f / ssum;
            float* So = g_S + ((size_t)layer * BM + bm0 + bm) * T * T + (size_t)l * T;
            if (v0) So[e] = e0 * inv;
            if (v1) So[e + 32] = e1 * inv;
        }
    }
#undef STAGE_B
}

// ---------------- channel mean + expand (fused) ----------------
template <int T, int P, bool TILE>
__global__ __launch_bounds__(256) void mean_expand_kernel(float* __restrict__ out) {
    constexpr int TT = T * T;
    __shared__ float sA[TT];
    int b = blockIdx.x, layer = blockIdx.y;
    const float* Sb = g_S + ((size_t)layer * BM + (size_t)b * MN) * TT;
    for (int r = threadIdx.x; r < TT; r += 256) {
        float s = 0.f;
#pragma unroll 5
        for (int m = 0; m < MN; m++) s += Sb[(size_t)m * TT + r];
        sA[r] = s * (1.0f / MN);
    }
    __syncthreads();
    float* ob = out + ((size_t)layer * BN + b) * LL;
    for (int i = threadIdx.x; i < LL; i += 256) {
        int l = i / LN, s = i - l * LN;
        int al = TILE ? (l % P) : (l / P);
        int as = TILE ? (s % P) : (s / P);
        ob[i] = sA[al * T + as];
    }
}

// ---------------- host orchestration ----------------
template <int T, int C, int P, bool TILE>
static void run_branch(int woff, float* outbase) {
    conv_embed_kernel<T, C><<<BM, 256>>>(woff);
    constexpr int QB = (T < 16) ? (16 / T) : 1;
    constexpr int NB = (T < 16) ? (8 * QB) : (128 / T);
    int nblk = (BM + NB - 1) / NB;
    cudaFuncSetAttribute(fused_kernel<T>, cudaFuncAttributeMaxDynamicSharedMemorySize, FUSED_SMEM);
    fused_kernel<T><<<nblk, 512, FUSED_SMEM>>>();
    mean_expand_kernel<T, P, TILE><<<dim3(BN, ELN), 256>>>(outbase);
}

extern "C" void kernel_launch(void* const* d_in, const int* in_sizes, int n_in,
                              void* d_out, int out_size) {
    const float* x = (const float*)d_in[0];
    const float* Wq = (const float*)d_in[7];
    const float* bq = (const float*)d_in[8];
    const float* Wk = (const float*)d_in[9];
    const float* bk = (const float*)d_in[10];
    float* out = (float*)d_out;

    k1_kernel<<<1250, 256>>>(x, Wq, Wk, bq, bk,
                             (const float*)d_in[1], (const float*)d_in[2],
                             (const float*)d_in[3], (const float*)d_in[4],
                             (const float*)d_in[5], (const float*)d_in[6]);
    meffT_kernel<<<dim3(256, ELN), 256>>>();

    run_branch<35, 3, 3, false>(0, out + (size_t)0 * BN * LL);
    run_branch<3, 35, 3, true>(2304, out + (size_t)9 * BN * LL);
    run_branch<21, 5, 5, false>(29184, out + (size_t)3 * BN * LL);
    run_branch<5, 21, 5, true>(33024, out + (size_t)12 * BN * LL);
    run_branch<15, 7, 7, false>(49152, out + (size_t)6 * BN * LL);
    run_branch<7, 15, 7, true>(54528, out + (size_t)15 * BN * LL);
}